// round 13
// baseline (speedup 1.0000x reference)
#include <cuda_runtime.h>
#include <cuda_fp16.h>
#include <stdint.h>

#define NB   2
#define SEQ  2048
#define DM   1024
#define NH   16
#define DKH  64

// ===================== device scratch (no allocations) =====================
__device__ __align__(128) __half g_xq[(size_t)NB*SEQ*DM];
__device__ __align__(128) __half g_xk[(size_t)NB*SEQ*DM];
__device__ __align__(128) __half g_xv[(size_t)NB*SEQ*DM];
__device__ __align__(128) __half g_wq[(size_t)DM*DM];
__device__ __align__(128) __half g_wk[(size_t)DM*DM];
__device__ __align__(128) __half g_wv[(size_t)DM*DM];
__device__ __align__(128) __half g_wo[(size_t)DM*DM];
__device__ __align__(128) __half g_q[(size_t)NB*NH*SEQ*DKH];    // pre-scaled by 0.125*log2(e)
__device__ __align__(128) __half g_k[(size_t)NB*NH*SEQ*DKH];
__device__ __align__(128) __half g_vT[(size_t)NB*NH*DKH*SEQ];
__device__ __align__(128) __half g_ctx[(size_t)NB*SEQ*DM];      // A-tiled for O-proj
__device__ uint32_t g_mbits[(size_t)NB*SEQ*64];   // [n][q][kv/32], bit=1 -> masked

// ===================== helpers =====================
__device__ __forceinline__ uint32_t smem_u32(const void* p) {
    uint32_t a;
    asm("{ .reg .u64 t; cvta.to.shared.u64 t, %1; cvt.u32.u64 %0, t; }" : "=r"(a) : "l"(p));
    return a;
}
__device__ __forceinline__ void ldsm4(uint32_t* r, uint32_t a) {
    asm volatile("ldmatrix.sync.aligned.m8n8.x4.shared.b16 {%0,%1,%2,%3}, [%4];"
        : "=r"(r[0]), "=r"(r[1]), "=r"(r[2]), "=r"(r[3]) : "r"(a));
}
__device__ __forceinline__ void mma_fp16(float* d, const uint32_t* a, uint32_t b0, uint32_t b1) {
    asm volatile(
        "mma.sync.aligned.m16n8k16.row.col.f32.f16.f16.f32 "
        "{%0,%1,%2,%3}, {%4,%5,%6,%7}, {%8,%9}, {%0,%1,%2,%3};"
        : "+f"(d[0]), "+f"(d[1]), "+f"(d[2]), "+f"(d[3])
        : "r"(a[0]), "r"(a[1]), "r"(a[2]), "r"(a[3]), "r"(b0), "r"(b1));
}
// f16-accumulator mma: d/c = 2 regs (4 halves): reg0 = row lr (c0 lo, c1 hi), reg1 = row lr+8
__device__ __forceinline__ void mma_fp16h(uint32_t* d, const uint32_t* a, uint32_t b0, uint32_t b1) {
    asm volatile(
        "mma.sync.aligned.m16n8k16.row.col.f16.f16.f16.f16 "
        "{%0,%1}, {%2,%3,%4,%5}, {%6,%7}, {%0,%1};"
        : "+r"(d[0]), "+r"(d[1])
        : "r"(a[0]), "r"(a[1]), "r"(a[2]), "r"(a[3]), "r"(b0), "r"(b1));
}
__device__ __forceinline__ uint32_t ex2h2(uint32_t x) {
    uint32_t d;
    asm("ex2.approx.f16x2 %0, %1;" : "=r"(d) : "r"(x));
    return d;
}
__device__ __forceinline__ uint32_t zmask2(uint32_t w, int sh) {
    uint32_t t = w >> sh;
    return (t & 1u) * 0x0000FFFFu + (t & 2u) * 0x7FFF8000u;
}

#define BULK_G2S(dst, src, bytes, mbar) \
    asm volatile("cp.async.bulk.shared::cta.global.mbarrier::complete_tx::bytes [%0], [%1], %2, [%3];" \
        :: "r"((uint32_t)(dst)), "l"(src), "r"((uint32_t)(bytes)), "r"((uint32_t)(mbar)) : "memory")
#define MBAR_INIT(mb, c)   asm volatile("mbarrier.init.shared.b64 [%0], %1;" :: "r"(mb), "r"((uint32_t)(c)) : "memory")
#define MBAR_EXPECT(mb, n) asm volatile("mbarrier.arrive.expect_tx.shared.b64 _, [%0], %1;" :: "r"(mb), "r"((uint32_t)(n)) : "memory")
#define MBAR_WAIT(mbar_addr, ph) do { \
    uint32_t _mb = (uint32_t)(mbar_addr); uint32_t _p = (uint32_t)(ph); uint32_t _done; \
    asm volatile("{\n\t.reg .pred p;\n\tmbarrier.try_wait.parity.acquire.cta.shared::cta.b64 p, [%1], %2;\n\tselp.b32 %0, 1, 0, p;\n\t}" \
        : "=r"(_done) : "r"(_mb), "r"(_p) : "memory"); \
    if (!_done) { \
        asm volatile("{\n\t.reg .pred P1;\n\tWL_%=:\n\tmbarrier.try_wait.parity.acquire.cta.shared::cta.b64 P1, [%0], %1, 0x989680;\n\t@P1 bra.uni WD_%=;\n\tbra.uni WL_%=;\n\tWD_%=:\n\t}" \
            :: "r"(_mb), "r"(_p) : "memory"); \
    } } while (0)

#define ASWZ(r, ch) ((uint32_t)(((r) << 7) + ((((ch) ^ ((r) & 7))) << 4)))

__device__ __forceinline__ uint32_t pack2h(float a, float b) {
    __half2 h = __floats2half2_rn(a, b);
    return *(uint32_t*)&h;
}
__device__ __forceinline__ float2 h2f2(uint32_t u) {
    return __half22float2(*(__half2*)&u);
}
#define ONES_H2 0x3C003C00u   // half2 (1.0, 1.0)

// ===================== prep: convert + tile-swizzle =====================
__global__ void cvt_all_kernel(
    const float* __restrict__ q,  const float* __restrict__ k,  const float* __restrict__ v,
    const float* __restrict__ Wq, const float* __restrict__ Wk, const float* __restrict__ Wv,
    const float* __restrict__ Wo)
{
    const int INPC = NB * SEQ * DM / 8;
    const int WC   = DM * DM / 8;
    int gid = blockIdx.x * blockDim.x + threadIdx.x;
    const float* src;
    char* dstb;
    int e;
    bool isA;
    if (gid < 3 * INPC) {
        int seg = gid / INPC;
        e = gid - seg * INPC;
        src = (seg == 0) ? q : (seg == 1) ? k : v;
        dstb = (char*)((seg == 0) ? g_xq : (seg == 1) ? g_xk : g_xv);
        isA = true;
    } else {
        int r2 = gid - 3 * INPC;
        int seg = r2 / WC;
        if (seg >= 4) return;
        e = r2 - seg * WC;
        src = (seg == 0) ? Wq : (seg == 1) ? Wk : (seg == 2) ? Wv : Wo;
        dstb = (char*)((seg == 0) ? g_wq : (seg == 1) ? g_wk : (seg == 2) ? g_wv : g_wo);
        isA = false;
    }
    int row = e >> 7;
    int ch8 = e & 127;
    int kchunk = ch8 >> 3, ch = ch8 & 7;
    size_t off;
    if (isA) off = ((size_t)((row >> 8) * 16 + kchunk) << 15) + ASWZ(row & 255, ch);
    else     off = ((size_t)((row >> 7) * 16 + kchunk) << 14) + ASWZ(row & 127, ch);
    const float* s = src + (size_t)row * DM + ch8 * 8;
    float4 x0 = *(const float4*)s;
    float4 x1 = *(const float4*)(s + 4);
    uint4 o;
    o.x = pack2h(x0.x, x0.y);
    o.y = pack2h(x0.z, x0.w);
    o.z = pack2h(x1.x, x1.y);
    o.w = pack2h(x1.z, x1.w);
    *(uint4*)(dstb + off) = o;
}

__global__ void maskpack_kernel(const int* __restrict__ mask)
{
    int w = blockIdx.x * blockDim.x + threadIdx.x;
    if (w >= NB * SEQ * 64) return;
    const int* p = mask + (size_t)w * 32;
    uint32_t bits = 0;
#pragma unroll
    for (int j = 0; j < 32; j += 4) {
        int4 m4 = *(const int4*)(p + j);
        bits |= (m4.x ? 1u : 0u) << j       | (m4.y ? 1u : 0u) << (j + 1)
              | (m4.z ? 1u : 0u) << (j + 2) | (m4.w ? 1u : 0u) << (j + 3);
    }
    g_mbits[w] = bits;
}

// ===================== projection GEMM: tile 256x128, warp 64x64, bulk loads =====================
#define PROJ_SMEM (2 * 49152 + 16)

template<int MODE>   // 0: Q tiled out, 1: fp32 out, 2: vT tiled out
__global__ void __launch_bounds__(256, 1) proj_kernel(
    const __half* __restrict__ A, const __half* __restrict__ W,
    const float* __restrict__ bias, void* out, float scale)
{
    extern __shared__ __align__(128) char smem[];
    uint32_t sb = smem_u32(smem);
    int tid = threadIdx.x, lane = tid & 31, warp = tid >> 5;
    int mblk = blockIdx.y, nblk = blockIdx.x;
    int bm = mblk * 256, bn = nblk * 128;
    uint32_t mb0 = sb + 2 * 49152, mb1 = mb0 + 8;

    if (tid == 0) { MBAR_INIT(mb0, 1); MBAR_INIT(mb1, 1); }
    __syncthreads();
    if (tid == 0) {
        MBAR_EXPECT(mb0, 49152);
        BULK_G2S(sb,         (const char*)A + ((size_t)(mblk * 16 + 0) << 15), 32768, mb0);
        BULK_G2S(sb + 32768, (const char*)W + ((size_t)(nblk * 16 + 0) << 14), 16384, mb0);
    }

    int wm = (warp >> 1) * 64, wn = (warp & 1) * 64;
    int a_r = (lane & 7) + ((lane >> 3) & 1) * 8;
    int a_c = lane >> 4;
    int b_r = (lane & 7) + (lane >> 4) * 8;
    int b_c = (lane >> 3) & 1;

    float acc[4][8][4];
#pragma unroll
    for (int i = 0; i < 4; i++)
#pragma unroll
        for (int j = 0; j < 8; j++)
#pragma unroll
            for (int t = 0; t < 4; t++) acc[i][j][t] = 0.0f;

    for (int c = 0; c < 16; c++) {
        MBAR_WAIT((c & 1) ? mb1 : mb0, (c >> 1) & 1);
        __syncthreads();
        if (c + 1 < 16 && tid == 0) {
            uint32_t st = sb + ((c + 1) & 1) * 49152;
            uint32_t mbx = ((c + 1) & 1) ? mb1 : mb0;
            MBAR_EXPECT(mbx, 49152);
            BULK_G2S(st,         (const char*)A + ((size_t)(mblk * 16 + c + 1) << 15), 32768, mbx);
            BULK_G2S(st + 32768, (const char*)W + ((size_t)(nblk * 16 + c + 1) << 14), 16384, mbx);
        }
        uint32_t ab = sb + (c & 1) * 49152;
        uint32_t wb = ab + 32768;
#pragma unroll
        for (int k16 = 0; k16 < 4; k16++) {
            uint32_t bh[4][4];
#pragma unroll
            for (int ngp = 0; ngp < 4; ngp++)
                ldsm4(bh[ngp], wb + ASWZ(wn + ngp * 16 + b_r, k16 * 2 + b_c));
#pragma unroll
            for (int mt = 0; mt < 4; mt++) {
                uint32_t ah[4];
                ldsm4(ah, ab + ASWZ(wm + mt * 16 + a_r, k16 * 2 + a_c));
#pragma unroll
                for (int ngp = 0; ngp < 4; ngp++) {
                    mma_fp16(acc[mt][2 * ngp],     ah, bh[ngp][0], bh[ngp][1]);
                    mma_fp16(acc[mt][2 * ngp + 1], ah, bh[ngp][2], bh[ngp][3]);
                }
            }
        }
    }

    int lr = lane >> 2, lc = (lane & 3) * 2;
#pragma unroll
    for (int mt = 0; mt < 4; mt++) {
#pragma unroll
        for (int i = 0; i < 2; i++) {
            int m = bm + wm + mt * 16 + lr + i * 8;
            int n2 = m >> 11, qq = m & (SEQ - 1);
#pragma unroll
            for (int n8 = 0; n8 < 8; n8++) {
                int o = bn + wn + n8 * 8 + lc;
                float v0 = (acc[mt][n8][2 * i + 0] + __ldg(bias + o))     * scale;
                float v1 = (acc[mt][n8][2 * i + 1] + __ldg(bias + o + 1)) * scale;
                if (MODE == 1) {
                    *(float2*)((float*)out + (size_t)m * DM + o) = make_float2(v0, v1);
                } else {
                    int hh = o >> 6, dd = o & 63;
                    if (MODE == 0) {
                        size_t off = ((size_t)((n2 * NH + hh) * 8 + (qq >> 8)) << 15)
                                   + ASWZ(qq & 255, dd >> 3) + (dd & 7) * 2;
                        *(uint32_t*)((char*)out + off) = pack2h(v0, v1);
                    } else {
                        size_t off = ((size_t)((n2 * NH + hh) * 32 + (qq >> 6)) << 13);
                        uint32_t c1 = ASWZ(dd,     (qq >> 3) & 7) + (qq & 7) * 2;
                        uint32_t c2 = ASWZ(dd + 1, (qq >> 3) & 7) + (qq & 7) * 2;
                        *(__half*)((char*)out + off + c1) = __float2half_rn(v0);
                        *(__half*)((char*)out + off + c2) = __float2half_rn(v1);
                    }
                }
            }
        }
    }
}

// K projection epilogue variant (64-row 8KB tiles)
__global__ void __launch_bounds__(256, 1) projk_kernel(
    const __half* __restrict__ A, const __half* __restrict__ W,
    const float* __restrict__ bias, void* out)
{
    extern __shared__ __align__(128) char smem[];
    uint32_t sb = smem_u32(smem);
    int tid = threadIdx.x, lane = tid & 31, warp = tid >> 5;
    int mblk = blockIdx.y, nblk = blockIdx.x;
    int bm = mblk * 256, bn = nblk * 128;
    uint32_t mb0 = sb + 2 * 49152, mb1 = mb0 + 8;

    if (tid == 0) { MBAR_INIT(mb0, 1); MBAR_INIT(mb1, 1); }
    __syncthreads();
    if (tid == 0) {
        MBAR_EXPECT(mb0, 49152);
        BULK_G2S(sb,         (const char*)A + ((size_t)(mblk * 16) << 15), 32768, mb0);
        BULK_G2S(sb + 32768, (const char*)W + ((size_t)(nblk * 16) << 14), 16384, mb0);
    }
    int wm = (warp >> 1) * 64, wn = (warp & 1) * 64;
    int a_r = (lane & 7) + ((lane >> 3) & 1) * 8;
    int a_c = lane >> 4;
    int b_r = (lane & 7) + (lane >> 4) * 8;
    int b_c = (lane >> 3) & 1;

    float acc[4][8][4];
#pragma unroll
    for (int i = 0; i < 4; i++)
#pragma unroll
        for (int j = 0; j < 8; j++)
#pragma unroll
            for (int t = 0; t < 4; t++) acc[i][j][t] = 0.0f;

    for (int c = 0; c < 16; c++) {
        MBAR_WAIT((c & 1) ? mb1 : mb0, (c >> 1) & 1);
        __syncthreads();
        if (c + 1 < 16 && tid == 0) {
            uint32_t st = sb + ((c + 1) & 1) * 49152;
            uint32_t mbx = ((c + 1) & 1) ? mb1 : mb0;
            MBAR_EXPECT(mbx, 49152);
            BULK_G2S(st,         (const char*)A + ((size_t)(mblk * 16 + c + 1) << 15), 32768, mbx);
            BULK_G2S(st + 32768, (const char*)W + ((size_t)(nblk * 16 + c + 1) << 14), 16384, mbx);
        }
        uint32_t ab = sb + (c & 1) * 49152;
        uint32_t wb = ab + 32768;
#pragma unroll
        for (int k16 = 0; k16 < 4; k16++) {
            uint32_t bh[4][4];
#pragma unroll
            for (int ngp = 0; ngp < 4; ngp++)
                ldsm4(bh[ngp], wb + ASWZ(wn + ngp * 16 + b_r, k16 * 2 + b_c));
#pragma unroll
            for (int mt = 0; mt < 4; mt++) {
                uint32_t ah[4];
                ldsm4(ah, ab + ASWZ(wm + mt * 16 + a_r, k16 * 2 + a_c));
#pragma unroll
                for (int ngp = 0; ngp < 4; ngp++) {
                    mma_fp16(acc[mt][2 * ngp],     ah, bh[ngp][0], bh[ngp][1]);
                    mma_fp16(acc[mt][2 * ngp + 1], ah, bh[ngp][2], bh[ngp][3]);
                }
            }
        }
    }
    int lr = lane >> 2, lc = (lane & 3) * 2;
#pragma unroll
    for (int mt = 0; mt < 4; mt++) {
#pragma unroll
        for (int i = 0; i < 2; i++) {
            int m = bm + wm + mt * 16 + lr + i * 8;
            int n2 = m >> 11, qq = m & (SEQ - 1);
#pragma unroll
            for (int n8 = 0; n8 < 8; n8++) {
                int o = bn + wn + n8 * 8 + lc;
                float v0 = acc[mt][n8][2 * i + 0] + __ldg(bias + o);
                float v1 = acc[mt][n8][2 * i + 1] + __ldg(bias + o + 1);
                int hh = o >> 6, dd = o & 63;
                size_t off = ((size_t)((n2 * NH + hh) * 32 + (qq >> 6)) << 13)
                           + ASWZ(qq & 63, dd >> 3) + (dd & 7) * 2;
                *(uint32_t*)((char*)out + off) = pack2h(v0, v1);
            }
        }
    }
}

// ===================== attention: f16 accumulators (S full, PV per-tile + f32 promote) =====================
#define ATT_SMEM (32768 + 3 * 16384 + 48)

__global__ void __launch_bounds__(256, 1) attn_kernel()
{
    extern __shared__ __align__(128) char smem[];
    uint32_t sb = smem_u32(smem);
    int tid = threadIdx.x, lane = tid & 31, warp = tid >> 5;   // warp 0..7, 32 rows each
    int qb = blockIdx.x, h = blockIdx.y, n = blockIdx.z;
    uint32_t qmb = sb + 81920;
    uint32_t fmb[3] = { sb + 81928, sb + 81936, sb + 81944 };

    const char* qsrc = (const char*)g_q  + ((size_t)((n * NH + h) * 8 + qb) << 15);
    const char* ksrc = (const char*)g_k  + ((size_t)((n * NH + h) * 32) << 13);
    const char* vsrc = (const char*)g_vT + ((size_t)((n * NH + h) * 32) << 13);
    const uint32_t* mbase = g_mbits + (size_t)n * SEQ * 64;

    if (tid == 0) {
        MBAR_INIT(qmb, 1);
        MBAR_INIT(fmb[0], 1); MBAR_INIT(fmb[1], 1); MBAR_INIT(fmb[2], 1);
    }
    __syncthreads();
    if (tid == 0) {
        MBAR_EXPECT(qmb, 32768);
        BULK_G2S(sb, qsrc, 32768, qmb);
#pragma unroll
        for (int p = 0; p < 2; p++) {
            MBAR_EXPECT(fmb[p], 16384);
            BULK_G2S(sb + 32768 + p * 16384,        ksrc + (size_t)p * 8192, 8192, fmb[p]);
            BULK_G2S(sb + 32768 + p * 16384 + 8192, vsrc + (size_t)p * 8192, 8192, fmb[p]);
        }
    }

    int a_r = (lane & 7) + ((lane >> 3) & 1) * 8;
    int a_c = lane >> 4;
    int b_r = (lane & 7) + (lane >> 4) * 8;
    int b_c = (lane >> 3) & 1;
    int lr = lane >> 2, lc = (lane & 3) * 2;
    int q0 = qb * 256 + warp * 32 + lr;

    uint32_t qa[4][2][4];
    float oacc[2][8][4];
    float lsumf[2][2];
#pragma unroll
    for (int mi = 0; mi < 2; mi++) {
#pragma unroll
        for (int ng = 0; ng < 8; ng++)
#pragma unroll
            for (int t = 0; t < 4; t++) oacc[mi][ng][t] = 0.0f;
        lsumf[mi][0] = 0.0f;
        lsumf[mi][1] = 0.0f;
    }

    for (int kt = 0; kt < 32; kt++) {
        int st = kt % 3;
        MBAR_WAIT(fmb[st], (kt / 3) & 1);
        __syncthreads();
        if (kt + 2 < 32 && tid == 0) {
            int s2 = (kt + 2) % 3;
            MBAR_EXPECT(fmb[s2], 16384);
            BULK_G2S(sb + 32768 + s2 * 16384,        ksrc + (size_t)(kt + 2) * 8192, 8192, fmb[s2]);
            BULK_G2S(sb + 32768 + s2 * 16384 + 8192, vsrc + (size_t)(kt + 2) * 8192, 8192, fmb[s2]);
        }
        if (kt == 0) {
            MBAR_WAIT(qmb, 0);
#pragma unroll
            for (int k16 = 0; k16 < 4; k16++)
#pragma unroll
                for (int mi = 0; mi < 2; mi++)
                    ldsm4(qa[k16][mi], sb + ASWZ(warp * 32 + mi * 16 + a_r, k16 * 2 + a_c));
        }
        uint2 mw[2][2];
#pragma unroll
        for (int mi = 0; mi < 2; mi++)
#pragma unroll
            for (int ri = 0; ri < 2; ri++)
                mw[mi][ri] = *(const uint2*)(mbase + (size_t)(q0 + mi * 16 + ri * 8) * 64 + 2 * kt);

        uint32_t kvb = sb + 32768 + st * 16384;

        // ---- S = Q K^T, f16 accumulators ----
        uint32_t sacc_h[2][8][2];
#pragma unroll
        for (int mi = 0; mi < 2; mi++)
#pragma unroll
            for (int ng = 0; ng < 8; ng++) {
                sacc_h[mi][ng][0] = 0u;
                sacc_h[mi][ng][1] = 0u;
            }
#pragma unroll
        for (int k16 = 0; k16 < 4; k16++) {
#pragma unroll
            for (int ngp = 0; ngp < 4; ngp++) {
                uint32_t bh[4];
                ldsm4(bh, kvb + ASWZ(ngp * 16 + b_r, k16 * 2 + b_c));
                mma_fp16h(sacc_h[0][2 * ngp],     qa[k16][0], bh[0], bh[1]);
                mma_fp16h(sacc_h[0][2 * ngp + 1], qa[k16][0], bh[2], bh[3]);
                mma_fp16h(sacc_h[1][2 * ngp],     qa[k16][1], bh[0], bh[1]);
                mma_fp16h(sacc_h[1][2 * ngp + 1], qa[k16][1], bh[2], bh[3]);
            }
        }

        // ---- softmax (direct ex2 on f16 frags) + PV in f16, promote after tile ----
        uint32_t pacc_h[2][8][2];
        uint32_t lacc_h[2][2];
#pragma unroll
        for (int mi = 0; mi < 2; mi++) {
#pragma unroll
            for (int ng = 0; ng < 8; ng++) {
                pacc_h[mi][ng][0] = 0u;
                pacc_h[mi][ng][1] = 0u;
            }
            lacc_h[mi][0] = 0u;
            lacc_h[mi][1] = 0u;
        }

#pragma unroll
        for (int g = 0; g < 4; g++) {
            uint32_t pa[2][4];
#pragma unroll
            for (int mi = 0; mi < 2; mi++) {
                uint32_t w0 = (g < 2) ? mw[mi][0].x : mw[mi][0].y;
                uint32_t w1 = (g < 2) ? mw[mi][1].x : mw[mi][1].y;
                int sh = ((g & 1) << 4) + lc;
                pa[mi][0] = ex2h2(sacc_h[mi][2 * g][0])     & ~zmask2(w0, sh);
                pa[mi][1] = ex2h2(sacc_h[mi][2 * g][1])     & ~zmask2(w1, sh);
                pa[mi][2] = ex2h2(sacc_h[mi][2 * g + 1][0]) & ~zmask2(w0, sh + 8);
                pa[mi][3] = ex2h2(sacc_h[mi][2 * g + 1][1]) & ~zmask2(w1, sh + 8);
                mma_fp16h(lacc_h[mi], pa[mi], ONES_H2, ONES_H2);
            }
#pragma unroll
            for (int ngd = 0; ngd < 4; ngd++) {
                uint32_t bh[4];
                ldsm4(bh, kvb + 8192 + ASWZ(ngd * 16 + b_r, g * 2 + b_c));
                mma_fp16h(pacc_h[0][2 * ngd],     pa[0], bh[0], bh[1]);
                mma_fp16h(pacc_h[0][2 * ngd + 1], pa[0], bh[2], bh[3]);
                mma_fp16h(pacc_h[1][2 * ngd],     pa[1], bh[0], bh[1]);
                mma_fp16h(pacc_h[1][2 * ngd + 1], pa[1], bh[2], bh[3]);
            }
        }

        // promote per-tile f16 partials to f32 master accumulators
#pragma unroll
        for (int mi = 0; mi < 2; mi++) {
#pragma unroll
            for (int ng = 0; ng < 8; ng++) {
                float2 f0 = h2f2(pacc_h[mi][ng][0]);
                float2 f1 = h2f2(pacc_h[mi][ng][1]);
                oacc[mi][ng][0] += f0.x;
                oacc[mi][ng][1] += f0.y;
                oacc[mi][ng][2] += f1.x;
                oacc[mi][ng][3] += f1.y;
            }
            lsumf[mi][0] += h2f2(lacc_h[mi][0]).x;   // row lr
            lsumf[mi][1] += h2f2(lacc_h[mi][1]).x;   // row lr+8
        }
    }

    // epilogue -> ctx in A-tiled layout: mblk = n*8 + qb, kchunk = h
    char* cbase = (char*)g_ctx + ((size_t)((n * 8 + qb) * 16 + h) << 15);
#pragma unroll
    for (int mi = 0; mi < 2; mi++) {
        float i0 = 1.0f / lsumf[mi][0];
        float i1 = 1.0f / lsumf[mi][1];
        int r = warp * 32 + mi * 16 + lr;
#pragma unroll
        for (int ng = 0; ng < 8; ng++) {
            *(uint32_t*)(cbase + ASWZ(r,     ng) + lc * 2) = pack2h(oacc[mi][ng][0] * i0, oacc[mi][ng][1] * i0);
            *(uint32_t*)(cbase + ASWZ(r + 8, ng) + lc * 2) = pack2h(oacc[mi][ng][2] * i1, oacc[mi][ng][3] * i1);
        }
    }
}

// ===================== launch =====================
extern "C" void kernel_launch(void* const* d_in, const int* in_sizes, int n_in,
                              void* d_out, int out_size)
{
    const float* q   = (const float*)d_in[0];
    const float* k   = (const float*)d_in[1];
    const float* v   = (const float*)d_in[2];
    const int*   msk = (const int*)d_in[3];
    const float* Wq  = (const float*)d_in[4];
    const float* bq  = (const float*)d_in[5];
    const float* Wk  = (const float*)d_in[6];
    const float* bk  = (const float*)d_in[7];
    const float* Wv  = (const float*)d_in[8];
    const float* bv  = (const float*)d_in[9];
    const float* Wo  = (const float*)d_in[10];
    const float* bo  = (const float*)d_in[11];
    float* out = (float*)d_out;

    __half *xq, *xk, *xv, *wq, *wk, *wv, *wo, *qp, *kp, *vt, *cx;
    cudaGetSymbolAddress((void**)&xq, g_xq);
    cudaGetSymbolAddress((void**)&xk, g_xk);
    cudaGetSymbolAddress((void**)&xv, g_xv);
    cudaGetSymbolAddress((void**)&wq, g_wq);
    cudaGetSymbolAddress((void**)&wk, g_wk);
    cudaGetSymbolAddress((void**)&wv, g_wv);
    cudaGetSymbolAddress((void**)&wo, g_wo);
    cudaGetSymbolAddress((void**)&qp, g_q);
    cudaGetSymbolAddress((void**)&kp, g_k);
    cudaGetSymbolAddress((void**)&vt, g_vT);
    cudaGetSymbolAddress((void**)&cx, g_ctx);

    cudaFuncSetAttribute(proj_kernel<0>, cudaFuncAttributeMaxDynamicSharedMemorySize, PROJ_SMEM);
    cudaFuncSetAttribute(proj_kernel<1>, cudaFuncAttributeMaxDynamicSharedMemorySize, PROJ_SMEM);
    cudaFuncSetAttribute(proj_kernel<2>, cudaFuncAttributeMaxDynamicSharedMemorySize, PROJ_SMEM);
    cudaFuncSetAttribute(projk_kernel,   cudaFuncAttributeMaxDynamicSharedMemorySize, PROJ_SMEM);
    cudaFuncSetAttribute(attn_kernel,    cudaFuncAttributeMaxDynamicSharedMemorySize, ATT_SMEM);

    const int TOTC = 3 * (NB * SEQ * DM / 8) + 4 * (DM * DM / 8);
    cvt_all_kernel<<<TOTC / 256, 256>>>(q, k, v, Wq, Wk, Wv, Wo);
    maskpack_kernel<<<NB * SEQ * 64 / 256, 256>>>(msk);

    dim3 pgrid(DM / 128, NB * SEQ / 256);
    proj_kernel<0><<<pgrid, 256, PROJ_SMEM>>>(xq, wq, bq, qp, 0.18033688011112043f);
    projk_kernel  <<<pgrid, 256, PROJ_SMEM>>>(xk, wk, bk, kp);
    proj_kernel<2><<<pgrid, 256, PROJ_SMEM>>>(xv, wv, bv, vt, 1.0f);

    attn_kernel<<<dim3(SEQ / 256, NH, NB), 256, ATT_SMEM>>>();

    proj_kernel<1><<<pgrid, 256, PROJ_SMEM>>>(cx, wo, bo, out, 1.0f);
}

// round 14
// speedup vs baseline: 1.0251x; 1.0251x over previous
#include <cuda_runtime.h>
#include <cuda_fp16.h>
#include <stdint.h>

#define NB   2
#define SEQ  2048
#define DM   1024
#define NH   16
#define DKH  64

// ===================== device scratch (no allocations) =====================
__device__ __align__(128) __half g_xq[(size_t)NB*SEQ*DM];
__device__ __align__(128) __half g_xk[(size_t)NB*SEQ*DM];
__device__ __align__(128) __half g_xv[(size_t)NB*SEQ*DM];
__device__ __align__(128) __half g_wq[(size_t)DM*DM];
__device__ __align__(128) __half g_wk[(size_t)DM*DM];
__device__ __align__(128) __half g_wv[(size_t)DM*DM];
__device__ __align__(128) __half g_wo[(size_t)DM*DM];
__device__ __align__(128) __half g_q[(size_t)NB*NH*SEQ*DKH];    // pre-scaled by 0.125*log2(e)
__device__ __align__(128) __half g_k[(size_t)NB*NH*SEQ*DKH];
__device__ __align__(128) __half g_vT[(size_t)NB*NH*DKH*SEQ];
__device__ __align__(128) __half g_ctx[(size_t)NB*SEQ*DM];      // A-tiled for O-proj
__device__ uint32_t g_mbits[(size_t)NB*SEQ*64];   // [n][q][kv/32], bit=1 -> masked

// ===================== helpers =====================
__device__ __forceinline__ uint32_t smem_u32(const void* p) {
    uint32_t a;
    asm("{ .reg .u64 t; cvta.to.shared.u64 t, %1; cvt.u32.u64 %0, t; }" : "=r"(a) : "l"(p));
    return a;
}
__device__ __forceinline__ void ldsm4(uint32_t* r, uint32_t a) {
    asm volatile("ldmatrix.sync.aligned.m8n8.x4.shared.b16 {%0,%1,%2,%3}, [%4];"
        : "=r"(r[0]), "=r"(r[1]), "=r"(r[2]), "=r"(r[3]) : "r"(a));
}
__device__ __forceinline__ void mma_fp16(float* d, const uint32_t* a, uint32_t b0, uint32_t b1) {
    asm volatile(
        "mma.sync.aligned.m16n8k16.row.col.f32.f16.f16.f32 "
        "{%0,%1,%2,%3}, {%4,%5,%6,%7}, {%8,%9}, {%0,%1,%2,%3};"
        : "+f"(d[0]), "+f"(d[1]), "+f"(d[2]), "+f"(d[3])
        : "r"(a[0]), "r"(a[1]), "r"(a[2]), "r"(a[3]), "r"(b0), "r"(b1));
}
__device__ __forceinline__ uint32_t cvt2h(float h, float l) {
    uint32_t d;
    asm("cvt.rn.f16x2.f32 %0, %1, %2;" : "=r"(d) : "f"(h), "f"(l));
    return d;
}
__device__ __forceinline__ uint32_t ex2h2(uint32_t x) {
    uint32_t d;
    asm("ex2.approx.f16x2 %0, %1;" : "=r"(d) : "r"(x));
    return d;
}
__device__ __forceinline__ uint32_t hadd2(uint32_t a, uint32_t b) {
    uint32_t d;
    asm("add.rn.f16x2 %0, %1, %2;" : "=r"(d) : "r"(a), "r"(b));
    return d;
}
__device__ __forceinline__ uint32_t zmask2(uint32_t w, int sh) {
    uint32_t t = w >> sh;
    return (t & 1u) * 0x0000FFFFu + (t & 2u) * 0x7FFF8000u;
}

#define BULK_G2S(dst, src, bytes, mbar) \
    asm volatile("cp.async.bulk.shared::cta.global.mbarrier::complete_tx::bytes [%0], [%1], %2, [%3];" \
        :: "r"((uint32_t)(dst)), "l"(src), "r"((uint32_t)(bytes)), "r"((uint32_t)(mbar)) : "memory")
#define MBAR_INIT(mb, c)   asm volatile("mbarrier.init.shared.b64 [%0], %1;" :: "r"(mb), "r"((uint32_t)(c)) : "memory")
#define MBAR_EXPECT(mb, n) asm volatile("mbarrier.arrive.expect_tx.shared.b64 _, [%0], %1;" :: "r"(mb), "r"((uint32_t)(n)) : "memory")
#define MBAR_WAIT(mbar_addr, ph) do { \
    uint32_t _mb = (uint32_t)(mbar_addr); uint32_t _p = (uint32_t)(ph); uint32_t _done; \
    asm volatile("{\n\t.reg .pred p;\n\tmbarrier.try_wait.parity.acquire.cta.shared::cta.b64 p, [%1], %2;\n\tselp.b32 %0, 1, 0, p;\n\t}" \
        : "=r"(_done) : "r"(_mb), "r"(_p) : "memory"); \
    if (!_done) { \
        asm volatile("{\n\t.reg .pred P1;\n\tWL_%=:\n\tmbarrier.try_wait.parity.acquire.cta.shared::cta.b64 P1, [%0], %1, 0x989680;\n\t@P1 bra.uni WD_%=;\n\tbra.uni WL_%=;\n\tWD_%=:\n\t}" \
            :: "r"(_mb), "r"(_p) : "memory"); \
    } } while (0)

#define ASWZ(r, ch) ((uint32_t)(((r) << 7) + ((((ch) ^ ((r) & 7))) << 4)))

__device__ __forceinline__ uint32_t pack2h(float a, float b) {
    __half2 h = __floats2half2_rn(a, b);
    return *(uint32_t*)&h;
}
__device__ __forceinline__ float2 h2f2(uint32_t u) {
    return __half22float2(*(__half2*)&u);
}

// ===================== prep: convert + tile-swizzle =====================
__global__ void cvt_all_kernel(
    const float* __restrict__ q,  const float* __restrict__ k,  const float* __restrict__ v,
    const float* __restrict__ Wq, const float* __restrict__ Wk, const float* __restrict__ Wv,
    const float* __restrict__ Wo)
{
    const int INPC = NB * SEQ * DM / 8;
    const int WC   = DM * DM / 8;
    int gid = blockIdx.x * blockDim.x + threadIdx.x;
    const float* src;
    char* dstb;
    int e;
    bool isA;
    if (gid < 3 * INPC) {
        int seg = gid / INPC;
        e = gid - seg * INPC;
        src = (seg == 0) ? q : (seg == 1) ? k : v;
        dstb = (char*)((seg == 0) ? g_xq : (seg == 1) ? g_xk : g_xv);
        isA = true;
    } else {
        int r2 = gid - 3 * INPC;
        int seg = r2 / WC;
        if (seg >= 4) return;
        e = r2 - seg * WC;
        src = (seg == 0) ? Wq : (seg == 1) ? Wk : (seg == 2) ? Wv : Wo;
        dstb = (char*)((seg == 0) ? g_wq : (seg == 1) ? g_wk : (seg == 2) ? g_wv : g_wo);
        isA = false;
    }
    int row = e >> 7;
    int ch8 = e & 127;
    int kchunk = ch8 >> 3, ch = ch8 & 7;
    size_t off;
    if (isA) off = ((size_t)((row >> 8) * 16 + kchunk) << 15) + ASWZ(row & 255, ch);
    else     off = ((size_t)((row >> 7) * 16 + kchunk) << 14) + ASWZ(row & 127, ch);
    const float* s = src + (size_t)row * DM + ch8 * 8;
    float4 x0 = *(const float4*)s;
    float4 x1 = *(const float4*)(s + 4);
    uint4 o;
    o.x = pack2h(x0.x, x0.y);
    o.y = pack2h(x0.z, x0.w);
    o.z = pack2h(x1.x, x1.y);
    o.w = pack2h(x1.z, x1.w);
    *(uint4*)(dstb + off) = o;
}

__global__ void maskpack_kernel(const int* __restrict__ mask)
{
    int w = blockIdx.x * blockDim.x + threadIdx.x;
    if (w >= NB * SEQ * 64) return;
    const int* p = mask + (size_t)w * 32;
    uint32_t bits = 0;
#pragma unroll
    for (int j = 0; j < 32; j += 4) {
        int4 m4 = *(const int4*)(p + j);
        bits |= (m4.x ? 1u : 0u) << j       | (m4.y ? 1u : 0u) << (j + 1)
              | (m4.z ? 1u : 0u) << (j + 2) | (m4.w ? 1u : 0u) << (j + 3);
    }
    g_mbits[w] = bits;
}

// ===================== fused Q/K/V projection (z selects), tile 256x128, bulk =====================
#define PROJ_SMEM (2 * 49152 + 16)

__global__ void __launch_bounds__(256, 1) proj_qkv_kernel(
    const float* __restrict__ bq, const float* __restrict__ bk, const float* __restrict__ bv)
{
    int z = blockIdx.z;
    const __half* A = (z == 0) ? g_xq : (z == 1) ? g_xk : g_xv;
    const __half* W = (z == 0) ? g_wq : (z == 1) ? g_wk : g_wv;
    const float* bias = (z == 0) ? bq : (z == 1) ? bk : bv;
    float scale = (z == 0) ? 0.18033688011112043f : 1.0f;

    extern __shared__ __align__(128) char smem[];
    uint32_t sb = smem_u32(smem);
    int tid = threadIdx.x, lane = tid & 31, warp = tid >> 5;
    int mblk = blockIdx.y, nblk = blockIdx.x;
    uint32_t mb0 = sb + 2 * 49152, mb1 = mb0 + 8;

    if (tid == 0) { MBAR_INIT(mb0, 1); MBAR_INIT(mb1, 1); }
    __syncthreads();
    if (tid == 0) {
        MBAR_EXPECT(mb0, 49152);
        BULK_G2S(sb,         (const char*)A + ((size_t)(mblk * 16 + 0) << 15), 32768, mb0);
        BULK_G2S(sb + 32768, (const char*)W + ((size_t)(nblk * 16 + 0) << 14), 16384, mb0);
    }

    int wm = (warp >> 1) * 64, wn = (warp & 1) * 64;
    int a_r = (lane & 7) + ((lane >> 3) & 1) * 8;
    int a_c = lane >> 4;
    int b_r = (lane & 7) + (lane >> 4) * 8;
    int b_c = (lane >> 3) & 1;

    float acc[4][8][4];
#pragma unroll
    for (int i = 0; i < 4; i++)
#pragma unroll
        for (int j = 0; j < 8; j++)
#pragma unroll
            for (int t = 0; t < 4; t++) acc[i][j][t] = 0.0f;

    for (int c = 0; c < 16; c++) {
        MBAR_WAIT((c & 1) ? mb1 : mb0, (c >> 1) & 1);
        __syncthreads();
        if (c + 1 < 16 && tid == 0) {
            uint32_t st = sb + ((c + 1) & 1) * 49152;
            uint32_t mbx = ((c + 1) & 1) ? mb1 : mb0;
            MBAR_EXPECT(mbx, 49152);
            BULK_G2S(st,         (const char*)A + ((size_t)(mblk * 16 + c + 1) << 15), 32768, mbx);
            BULK_G2S(st + 32768, (const char*)W + ((size_t)(nblk * 16 + c + 1) << 14), 16384, mbx);
        }
        uint32_t ab = sb + (c & 1) * 49152;
        uint32_t wb = ab + 32768;
#pragma unroll
        for (int k16 = 0; k16 < 4; k16++) {
            uint32_t bh[4][4];
#pragma unroll
            for (int ngp = 0; ngp < 4; ngp++)
                ldsm4(bh[ngp], wb + ASWZ(wn + ngp * 16 + b_r, k16 * 2 + b_c));
#pragma unroll
            for (int mt = 0; mt < 4; mt++) {
                uint32_t ah[4];
                ldsm4(ah, ab + ASWZ(wm + mt * 16 + a_r, k16 * 2 + a_c));
#pragma unroll
                for (int ngp = 0; ngp < 4; ngp++) {
                    mma_fp16(acc[mt][2 * ngp],     ah, bh[ngp][0], bh[ngp][1]);
                    mma_fp16(acc[mt][2 * ngp + 1], ah, bh[ngp][2], bh[ngp][3]);
                }
            }
        }
    }

    int lr = lane >> 2, lc = (lane & 3) * 2;
    char* outq = (char*)g_q;
    char* outk = (char*)g_k;
    char* outv = (char*)g_vT;
#pragma unroll
    for (int mt = 0; mt < 4; mt++) {
#pragma unroll
        for (int i = 0; i < 2; i++) {
            int m = mblk * 256 + wm + mt * 16 + lr + i * 8;
            int n2 = m >> 11, qq = m & (SEQ - 1);
#pragma unroll
            for (int n8 = 0; n8 < 8; n8++) {
                int o = nblk * 128 + wn + n8 * 8 + lc;
                float v0 = (acc[mt][n8][2 * i + 0] + __ldg(bias + o))     * scale;
                float v1 = (acc[mt][n8][2 * i + 1] + __ldg(bias + o + 1)) * scale;
                int hh = o >> 6, dd = o & 63;
                if (z == 0) {
                    size_t off = ((size_t)((n2 * NH + hh) * 8 + (qq >> 8)) << 15)
                               + ASWZ(qq & 255, dd >> 3) + (dd & 7) * 2;
                    *(uint32_t*)(outq + off) = pack2h(v0, v1);
                } else if (z == 1) {
                    size_t off = ((size_t)((n2 * NH + hh) * 32 + (qq >> 6)) << 13)
                               + ASWZ(qq & 63, dd >> 3) + (dd & 7) * 2;
                    *(uint32_t*)(outk + off) = pack2h(v0, v1);
                } else {
                    size_t off = ((size_t)((n2 * NH + hh) * 32 + (qq >> 6)) << 13);
                    uint32_t c1 = ASWZ(dd,     (qq >> 3) & 7) + (qq & 7) * 2;
                    uint32_t c2 = ASWZ(dd + 1, (qq >> 3) & 7) + (qq & 7) * 2;
                    *(__half*)(outv + off + c1) = __float2half_rn(v0);
                    *(__half*)(outv + off + c2) = __float2half_rn(v1);
                }
            }
        }
    }
}

// ---- O projection: fp32 output ----
__global__ void __launch_bounds__(256, 1) proj_o_kernel(const float* __restrict__ bias,
                                                        float* __restrict__ out)
{
    extern __shared__ __align__(128) char smem[];
    uint32_t sb = smem_u32(smem);
    int tid = threadIdx.x, lane = tid & 31, warp = tid >> 5;
    int mblk = blockIdx.y, nblk = blockIdx.x;
    uint32_t mb0 = sb + 2 * 49152, mb1 = mb0 + 8;

    if (tid == 0) { MBAR_INIT(mb0, 1); MBAR_INIT(mb1, 1); }
    __syncthreads();
    if (tid == 0) {
        MBAR_EXPECT(mb0, 49152);
        BULK_G2S(sb,         (const char*)g_ctx + ((size_t)(mblk * 16) << 15), 32768, mb0);
        BULK_G2S(sb + 32768, (const char*)g_wo  + ((size_t)(nblk * 16) << 14), 16384, mb0);
    }
    int wm = (warp >> 1) * 64, wn = (warp & 1) * 64;
    int a_r = (lane & 7) + ((lane >> 3) & 1) * 8;
    int a_c = lane >> 4;
    int b_r = (lane & 7) + (lane >> 4) * 8;
    int b_c = (lane >> 3) & 1;

    float acc[4][8][4];
#pragma unroll
    for (int i = 0; i < 4; i++)
#pragma unroll
        for (int j = 0; j < 8; j++)
#pragma unroll
            for (int t = 0; t < 4; t++) acc[i][j][t] = 0.0f;

    for (int c = 0; c < 16; c++) {
        MBAR_WAIT((c & 1) ? mb1 : mb0, (c >> 1) & 1);
        __syncthreads();
        if (c + 1 < 16 && tid == 0) {
            uint32_t st = sb + ((c + 1) & 1) * 49152;
            uint32_t mbx = ((c + 1) & 1) ? mb1 : mb0;
            MBAR_EXPECT(mbx, 49152);
            BULK_G2S(st,         (const char*)g_ctx + ((size_t)(mblk * 16 + c + 1) << 15), 32768, mbx);
            BULK_G2S(st + 32768, (const char*)g_wo  + ((size_t)(nblk * 16 + c + 1) << 14), 16384, mbx);
        }
        uint32_t ab = sb + (c & 1) * 49152;
        uint32_t wb = ab + 32768;
#pragma unroll
        for (int k16 = 0; k16 < 4; k16++) {
            uint32_t bh[4][4];
#pragma unroll
            for (int ngp = 0; ngp < 4; ngp++)
                ldsm4(bh[ngp], wb + ASWZ(wn + ngp * 16 + b_r, k16 * 2 + b_c));
#pragma unroll
            for (int mt = 0; mt < 4; mt++) {
                uint32_t ah[4];
                ldsm4(ah, ab + ASWZ(wm + mt * 16 + a_r, k16 * 2 + a_c));
#pragma unroll
                for (int ngp = 0; ngp < 4; ngp++) {
                    mma_fp16(acc[mt][2 * ngp],     ah, bh[ngp][0], bh[ngp][1]);
                    mma_fp16(acc[mt][2 * ngp + 1], ah, bh[ngp][2], bh[ngp][3]);
                }
            }
        }
    }
    int lr = lane >> 2, lc = (lane & 3) * 2;
#pragma unroll
    for (int mt = 0; mt < 4; mt++) {
#pragma unroll
        for (int i = 0; i < 2; i++) {
            int m = mblk * 256 + wm + mt * 16 + lr + i * 8;
#pragma unroll
            for (int n8 = 0; n8 < 8; n8++) {
                int o = nblk * 128 + wn + n8 * 8 + lc;
                float v0 = acc[mt][n8][2 * i + 0] + __ldg(bias + o);
                float v1 = acc[mt][n8][2 * i + 1] + __ldg(bias + o + 1);
                *(float2*)(out + (size_t)m * DM + o) = make_float2(v0, v1);
            }
        }
    }
}

// ===================== attention: f32-acc MMA, HADD2 lsum, bulk KV ring =====================
#define ATT_SMEM (32768 + 3 * 16384 + 48)

__global__ void __launch_bounds__(256, 1) attn_kernel()
{
    extern __shared__ __align__(128) char smem[];
    uint32_t sb = smem_u32(smem);
    int tid = threadIdx.x, lane = tid & 31, warp = tid >> 5;   // warp 0..7, 32 rows each
    int qb = blockIdx.x, h = blockIdx.y, n = blockIdx.z;
    uint32_t qmb = sb + 81920;
    uint32_t fmb[3] = { sb + 81928, sb + 81936, sb + 81944 };

    const char* qsrc = (const char*)g_q  + ((size_t)((n * NH + h) * 8 + qb) << 15);
    const char* ksrc = (const char*)g_k  + ((size_t)((n * NH + h) * 32) << 13);
    const char* vsrc = (const char*)g_vT + ((size_t)((n * NH + h) * 32) << 13);
    const uint32_t* mbase = g_mbits + (size_t)n * SEQ * 64;

    if (tid == 0) {
        MBAR_INIT(qmb, 1);
        MBAR_INIT(fmb[0], 1); MBAR_INIT(fmb[1], 1); MBAR_INIT(fmb[2], 1);
    }
    __syncthreads();
    if (tid == 0) {
        MBAR_EXPECT(qmb, 32768);
        BULK_G2S(sb, qsrc, 32768, qmb);
#pragma unroll
        for (int p = 0; p < 2; p++) {
            MBAR_EXPECT(fmb[p], 16384);
            BULK_G2S(sb + 32768 + p * 16384,        ksrc + (size_t)p * 8192, 8192, fmb[p]);
            BULK_G2S(sb + 32768 + p * 16384 + 8192, vsrc + (size_t)p * 8192, 8192, fmb[p]);
        }
    }

    int a_r = (lane & 7) + ((lane >> 3) & 1) * 8;
    int a_c = lane >> 4;
    int b_r = (lane & 7) + (lane >> 4) * 8;
    int b_c = (lane >> 3) & 1;
    int lr = lane >> 2, lc = (lane & 3) * 2;
    int q0 = qb * 256 + warp * 32 + lr;

    uint32_t qa[4][2][4];
    float oacc[2][8][4];
    float lsumf[2][2];
#pragma unroll
    for (int mi = 0; mi < 2; mi++) {
#pragma unroll
        for (int ng = 0; ng < 8; ng++)
#pragma unroll
            for (int t = 0; t < 4; t++) oacc[mi][ng][t] = 0.0f;
        lsumf[mi][0] = 0.0f;
        lsumf[mi][1] = 0.0f;
    }

    for (int kt = 0; kt < 32; kt++) {
        int st = kt % 3;
        MBAR_WAIT(fmb[st], (kt / 3) & 1);
        __syncthreads();
        if (kt + 2 < 32 && tid == 0) {
            int s2 = (kt + 2) % 3;
            MBAR_EXPECT(fmb[s2], 16384);
            BULK_G2S(sb + 32768 + s2 * 16384,        ksrc + (size_t)(kt + 2) * 8192, 8192, fmb[s2]);
            BULK_G2S(sb + 32768 + s2 * 16384 + 8192, vsrc + (size_t)(kt + 2) * 8192, 8192, fmb[s2]);
        }
        if (kt == 0) {
            MBAR_WAIT(qmb, 0);
#pragma unroll
            for (int k16 = 0; k16 < 4; k16++)
#pragma unroll
                for (int mi = 0; mi < 2; mi++)
                    ldsm4(qa[k16][mi], sb + ASWZ(warp * 32 + mi * 16 + a_r, k16 * 2 + a_c));
        }
        uint2 mw[2][2];
#pragma unroll
        for (int mi = 0; mi < 2; mi++)
#pragma unroll
            for (int ri = 0; ri < 2; ri++)
                mw[mi][ri] = *(const uint2*)(mbase + (size_t)(q0 + mi * 16 + ri * 8) * 64 + 2 * kt);

        uint32_t kvb = sb + 32768 + st * 16384;

        // ---- S = Q K^T (f32 acc) ----
        float sacc[2][8][4];
#pragma unroll
        for (int mi = 0; mi < 2; mi++)
#pragma unroll
            for (int ng = 0; ng < 8; ng++)
#pragma unroll
                for (int t = 0; t < 4; t++) sacc[mi][ng][t] = 0.0f;

#pragma unroll
        for (int k16 = 0; k16 < 4; k16++) {
#pragma unroll
            for (int ngp = 0; ngp < 4; ngp++) {
                uint32_t bh[4];
                ldsm4(bh, kvb + ASWZ(ngp * 16 + b_r, k16 * 2 + b_c));
                mma_fp16(sacc[0][2 * ngp],     qa[k16][0], bh[0], bh[1]);
                mma_fp16(sacc[0][2 * ngp + 1], qa[k16][0], bh[2], bh[3]);
                mma_fp16(sacc[1][2 * ngp],     qa[k16][1], bh[0], bh[1]);
                mma_fp16(sacc[1][2 * ngp + 1], qa[k16][1], bh[2], bh[3]);
            }
        }

        // ---- softmax + PV; lsum via HADD2 on fma pipe (no ones-MMA) ----
        uint32_t lh[2][2] = {{0u, 0u}, {0u, 0u}};   // f16x2 per-tile row-sum partials
#pragma unroll
        for (int g = 0; g < 4; g++) {
            uint32_t pa[2][4];
#pragma unroll
            for (int mi = 0; mi < 2; mi++) {
                uint32_t w0 = (g < 2) ? mw[mi][0].x : mw[mi][0].y;
                uint32_t w1 = (g < 2) ? mw[mi][1].x : mw[mi][1].y;
                int sh = ((g & 1) << 4) + lc;
                const float* s0 = sacc[mi][2 * g];
                const float* s1 = sacc[mi][2 * g + 1];
                pa[mi][0] = ex2h2(cvt2h(s0[1], s0[0])) & ~zmask2(w0, sh);
                pa[mi][1] = ex2h2(cvt2h(s0[3], s0[2])) & ~zmask2(w1, sh);
                pa[mi][2] = ex2h2(cvt2h(s1[1], s1[0])) & ~zmask2(w0, sh + 8);
                pa[mi][3] = ex2h2(cvt2h(s1[3], s1[2])) & ~zmask2(w1, sh + 8);
                lh[mi][0] = hadd2(lh[mi][0], hadd2(pa[mi][0], pa[mi][2]));   // row lr
                lh[mi][1] = hadd2(lh[mi][1], hadd2(pa[mi][1], pa[mi][3]));   // row lr+8
            }
#pragma unroll
            for (int ngd = 0; ngd < 4; ngd++) {
                uint32_t bh[4];
                ldsm4(bh, kvb + 8192 + ASWZ(ngd * 16 + b_r, g * 2 + b_c));
                mma_fp16(oacc[0][2 * ngd],     pa[0], bh[0], bh[1]);
                mma_fp16(oacc[0][2 * ngd + 1], pa[0], bh[2], bh[3]);
                mma_fp16(oacc[1][2 * ngd],     pa[1], bh[0], bh[1]);
                mma_fp16(oacc[1][2 * ngd + 1], pa[1], bh[2], bh[3]);
            }
        }
        // promote per-tile f16 partials to f32
#pragma unroll
        for (int mi = 0; mi < 2; mi++) {
            float2 f0 = h2f2(lh[mi][0]);
            float2 f1 = h2f2(lh[mi][1]);
            lsumf[mi][0] += f0.x + f0.y;
            lsumf[mi][1] += f1.x + f1.y;
        }
    }

    // ---- epilogue: quad reduction for row sums, write ctx (A-tiled) ----
    char* cbase = (char*)g_ctx + ((size_t)((n * 8 + qb) * 16 + h) << 15);
#pragma unroll
    for (int mi = 0; mi < 2; mi++) {
#pragma unroll
        for (int ri = 0; ri < 2; ri++) {
            lsumf[mi][ri] += __shfl_xor_sync(0xffffffffu, lsumf[mi][ri], 1);
            lsumf[mi][ri] += __shfl_xor_sync(0xffffffffu, lsumf[mi][ri], 2);
        }
        float i0 = 1.0f / lsumf[mi][0];
        float i1 = 1.0f / lsumf[mi][1];
        int r = warp * 32 + mi * 16 + lr;
#pragma unroll
        for (int ng = 0; ng < 8; ng++) {
            *(uint32_t*)(cbase + ASWZ(r,     ng) + lc * 2) = pack2h(oacc[mi][ng][0] * i0, oacc[mi][ng][1] * i0);
            *(uint32_t*)(cbase + ASWZ(r + 8, ng) + lc * 2) = pack2h(oacc[mi][ng][2] * i1, oacc[mi][ng][3] * i1);
        }
    }
}

// ===================== launch =====================
extern "C" void kernel_launch(void* const* d_in, const int* in_sizes, int n_in,
                              void* d_out, int out_size)
{
    const float* q   = (const float*)d_in[0];
    const float* k   = (const float*)d_in[1];
    const float* v   = (const float*)d_in[2];
    const int*   msk = (const int*)d_in[3];
    const float* Wq  = (const float*)d_in[4];
    const float* bq  = (const float*)d_in[5];
    const float* Wk  = (const float*)d_in[6];
    const float* bk  = (const float*)d_in[7];
    const float* Wv  = (const float*)d_in[8];
    const float* bv  = (const float*)d_in[9];
    const float* Wo  = (const float*)d_in[10];
    const float* bo  = (const float*)d_in[11];
    float* out = (float*)d_out;

    cudaFuncSetAttribute(proj_qkv_kernel, cudaFuncAttributeMaxDynamicSharedMemorySize, PROJ_SMEM);
    cudaFuncSetAttribute(proj_o_kernel,   cudaFuncAttributeMaxDynamicSharedMemorySize, PROJ_SMEM);
    cudaFuncSetAttribute(attn_kernel,     cudaFuncAttributeMaxDynamicSharedMemorySize, ATT_SMEM);

    const int TOTC = 3 * (NB * SEQ * DM / 8) + 4 * (DM * DM / 8);
    cvt_all_kernel<<<TOTC / 256, 256>>>(q, k, v, Wq, Wk, Wv, Wo);
    maskpack_kernel<<<NB * SEQ * 64 / 256, 256>>>(msk);

    dim3 pgrid(DM / 128, NB * SEQ / 256, 3);
    proj_qkv_kernel<<<pgrid, 256, PROJ_SMEM>>>(bq, bk, bv);

    attn_kernel<<<dim3(SEQ / 256, NH, NB), 256, ATT_SMEM>>>();

    dim3 ogrid(DM / 128, NB * SEQ / 256);
    proj_o_kernel<<<ogrid, 256, PROJ_SMEM>>>(bo, out);
}

// round 15
// speedup vs baseline: 1.0261x; 1.0010x over previous
#include <cuda_runtime.h>
#include <cuda_fp16.h>
#include <stdint.h>

#define NB   2
#define SEQ  2048
#define DM   1024
#define NH   16
#define DKH  64

// ===================== device scratch (no allocations) =====================
__device__ __align__(16) __half g_xq[(size_t)NB*SEQ*DM];
__device__ __align__(16) __half g_xk[(size_t)NB*SEQ*DM];
__device__ __align__(16) __half g_xv[(size_t)NB*SEQ*DM];
__device__ __align__(16) __half g_wq[(size_t)DM*DM];
__device__ __align__(16) __half g_wk[(size_t)DM*DM];
__device__ __align__(16) __half g_wv[(size_t)DM*DM];
__device__ __align__(16) __half g_wo[(size_t)DM*DM];
__device__ __align__(16) __half g_q[(size_t)NB*NH*SEQ*DKH];     // pre-scaled by 0.125*log2(e)
__device__ __align__(16) __half g_k[(size_t)NB*NH*SEQ*DKH];
__device__ __align__(16) __half g_vT[(size_t)NB*NH*DKH*SEQ];
__device__ __align__(16) __half g_ctx[(size_t)NB*SEQ*DM];
__device__ uint32_t g_mbits[(size_t)NB*SEQ*64];   // [n][q][kv/32], bit=1 -> masked

// ===================== helpers =====================
__device__ __forceinline__ uint32_t smem_u32(const void* p) {
    uint32_t a;
    asm("{ .reg .u64 t; cvta.to.shared.u64 t, %1; cvt.u32.u64 %0, t; }" : "=r"(a) : "l"(p));
    return a;
}
__device__ __forceinline__ void ldsm4(uint32_t* r, uint32_t a) {
    asm volatile("ldmatrix.sync.aligned.m8n8.x4.shared.b16 {%0,%1,%2,%3}, [%4];"
        : "=r"(r[0]), "=r"(r[1]), "=r"(r[2]), "=r"(r[3]) : "r"(a));
}
__device__ __forceinline__ void mma_fp16(float* d, const uint32_t* a, uint32_t b0, uint32_t b1) {
    asm volatile(
        "mma.sync.aligned.m16n8k16.row.col.f32.f16.f16.f32 "
        "{%0,%1,%2,%3}, {%4,%5,%6,%7}, {%8,%9}, {%0,%1,%2,%3};"
        : "+f"(d[0]), "+f"(d[1]), "+f"(d[2]), "+f"(d[3])
        : "r"(a[0]), "r"(a[1]), "r"(a[2]), "r"(a[3]), "r"(b0), "r"(b1));
}
// pack two f32 into half2 (lo = l, hi = h)
__device__ __forceinline__ uint32_t cvt2h(float h, float l) {
    uint32_t d;
    asm("cvt.rn.f16x2.f32 %0, %1, %2;" : "=r"(d) : "f"(h), "f"(l));
    return d;
}
__device__ __forceinline__ uint32_t ex2h2(uint32_t x) {
    uint32_t d;
    asm("ex2.approx.f16x2 %0, %1;" : "=r"(d) : "r"(x));
    return d;
}
__device__ __forceinline__ uint32_t hadd2(uint32_t a, uint32_t b) {
    uint32_t d;
    asm("add.rn.f16x2 %0, %1, %2;" : "=r"(d) : "r"(a), "r"(b));
    return d;
}
// AND-pattern: halfword k is 0xFFFF where mask bit (sh+k) is SET (masked)
__device__ __forceinline__ uint32_t zmask2(uint32_t w, int sh) {
    uint32_t t = w >> sh;
    return (t & 1u) * 0x0000FFFFu + (t & 2u) * 0x7FFF8000u;
}
#define CP16(dst, src)  asm volatile("cp.async.cg.shared.global [%0], [%1], 16;" :: "r"(dst), "l"(src) : "memory")
#define CPCOMMIT()      asm volatile("cp.async.commit_group;" ::: "memory")
#define CPWAIT0()       asm volatile("cp.async.wait_group 0;" ::: "memory")

// 128-byte rows: SW128 swizzle on 16B chunks
#define ASWZ(r, ch) ((uint32_t)(((r) << 7) + ((((ch) ^ ((r) & 7))) << 4)))

__device__ __forceinline__ uint32_t pack2h(float a, float b) {
    __half2 h = __floats2half2_rn(a, b);
    return *(uint32_t*)&h;
}

#define ONES_H2 0x3C003C00u   // half2 (1.0, 1.0)

// ===================== prep: one fused convert kernel =====================
__global__ void cvt_all_kernel(
    const float* __restrict__ q,  const float* __restrict__ k,  const float* __restrict__ v,
    const float* __restrict__ Wq, const float* __restrict__ Wk, const float* __restrict__ Wv,
    const float* __restrict__ Wo)
{
    const int INP4 = NB * SEQ * DM / 4;   // 1048576
    const int W4   = DM * DM / 4;         // 262144
    int gid = blockIdx.x * blockDim.x + threadIdx.x;
    const float* src;
    __half* dst;
    int off;
    if (gid < 3 * INP4) {
        int seg = gid / INP4;
        off = gid - seg * INP4;
        src = (seg == 0) ? q : (seg == 1) ? k : v;
        dst = (seg == 0) ? g_xq : (seg == 1) ? g_xk : g_xv;
    } else {
        int r = gid - 3 * INP4;
        int seg = r / W4;
        if (seg >= 4) return;
        off = r - seg * W4;
        src = (seg == 0) ? Wq : (seg == 1) ? Wk : (seg == 2) ? Wv : Wo;
        dst = (seg == 0) ? g_wq : (seg == 1) ? g_wk : (seg == 2) ? g_wv : g_wo;
    }
    float4 x = ((const float4*)src)[off];
    uint2 o;
    o.x = pack2h(x.x, x.y);
    o.y = pack2h(x.z, x.w);
    ((uint2*)dst)[off] = o;
}

__global__ void maskpack_kernel(const int* __restrict__ mask)
{
    int w = blockIdx.x * blockDim.x + threadIdx.x;
    if (w >= NB * SEQ * 64) return;
    const int* p = mask + (size_t)w * 32;
    uint32_t bits = 0;
#pragma unroll
    for (int j = 0; j < 32; j += 4) {
        int4 m4 = *(const int4*)(p + j);
        bits |= (m4.x ? 1u : 0u) << j       | (m4.y ? 1u : 0u) << (j + 1)
              | (m4.z ? 1u : 0u) << (j + 2) | (m4.w ? 1u : 0u) << (j + 3);
    }
    g_mbits[w] = bits;
}

// ===================== projection GEMM core (2-stage cp.async) =====================
#define PROJ_SMEM 65536

__device__ __forceinline__ void proj_load(
    uint32_t sbase, int tid, int k0,
    const __half* __restrict__ A, const __half* __restrict__ W, int bm, int bn)
{
#pragma unroll
    for (int i = 0; i < 4; i++) {
        int idx = tid + i * 256;          // 0..1023 -> 128 rows x 8 chunks
        int r = idx >> 3, ch = idx & 7;
        uint32_t d = sbase + ASWZ(r, ch);
        CP16(d,         A + (size_t)(bm + r) * DM + k0 + ch * 8);
        CP16(d + 16384, W + (size_t)(bn + r) * DM + k0 + ch * 8);
    }
}

__device__ __forceinline__ void proj_mainloop(
    uint32_t sb, int tid, int lane, int warp,
    const __half* __restrict__ A, const __half* __restrict__ W,
    int bm, int bn, float acc[4][4][4])
{
    int wm = (warp >> 2) * 64;
    int wn = (warp & 3) * 32;
    int a_r = (lane & 7) + ((lane >> 3) & 1) * 8;
    int a_c = lane >> 4;
    int b_r = (lane & 7) + (lane >> 4) * 8;
    int b_c = (lane >> 3) & 1;

    proj_load(sb, tid, 0, A, W, bm, bn);
    CPCOMMIT();

    for (int c = 0; c < 16; c++) {
        CPWAIT0();
        __syncthreads();
        if (c + 1 < 16) {
            proj_load(sb + ((c + 1) & 1) * 32768, tid, (c + 1) * 64, A, W, bm, bn);
            CPCOMMIT();
        }
        uint32_t ab = sb + (c & 1) * 32768;
        uint32_t wb = ab + 16384;
#pragma unroll
        for (int k16 = 0; k16 < 4; k16++) {
            uint32_t bh0[4], bh1[4];
            ldsm4(bh0, wb + ASWZ(wn + b_r,      k16 * 2 + b_c));
            ldsm4(bh1, wb + ASWZ(wn + 16 + b_r, k16 * 2 + b_c));
#pragma unroll
            for (int mt = 0; mt < 4; mt++) {
                uint32_t ah[4];
                ldsm4(ah, ab + ASWZ(wm + mt * 16 + a_r, k16 * 2 + a_c));
                mma_fp16(acc[mt][0], ah, bh0[0], bh0[1]);
                mma_fp16(acc[mt][1], ah, bh0[2], bh0[3]);
                mma_fp16(acc[mt][2], ah, bh1[0], bh1[1]);
                mma_fp16(acc[mt][3], ah, bh1[2], bh1[3]);
            }
        }
    }
}

// ---- fused Q/K/V projection: grid.z selects which ----
__global__ void __launch_bounds__(256, 2) proj_qkv_kernel(
    const float* __restrict__ bq, const float* __restrict__ bk, const float* __restrict__ bv)
{
    int z = blockIdx.z;
    const __half* A = (z == 0) ? g_xq : (z == 1) ? g_xk : g_xv;
    const __half* W = (z == 0) ? g_wq : (z == 1) ? g_wk : g_wv;
    const float* bias = (z == 0) ? bq : (z == 1) ? bk : bv;
    __half* out = (z == 0) ? g_q : (z == 1) ? g_k : g_vT;
    float scale = (z == 0) ? 0.18033688011112043f : 1.0f;   // 0.125 * log2(e) for Q

    extern __shared__ __align__(128) char smem[];
    uint32_t sb = smem_u32(smem);
    int tid = threadIdx.x, lane = tid & 31, warp = tid >> 5;
    int bm = blockIdx.y * 128, bn = blockIdx.x * 128;

    float acc[4][4][4];
#pragma unroll
    for (int i = 0; i < 4; i++)
#pragma unroll
        for (int j = 0; j < 4; j++)
#pragma unroll
            for (int t = 0; t < 4; t++) acc[i][j][t] = 0.0f;

    proj_mainloop(sb, tid, lane, warp, A, W, bm, bn, acc);

    int wm = (warp >> 2) * 64, wn = (warp & 3) * 32;
    int lr = lane >> 2, lc = (lane & 3) * 2;
#pragma unroll
    for (int mt = 0; mt < 4; mt++) {
#pragma unroll
        for (int i = 0; i < 2; i++) {
            int m = bm + wm + mt * 16 + lr + i * 8;
            int nb2 = m >> 11, q = m & (SEQ - 1);
#pragma unroll
            for (int nt = 0; nt < 4; nt++) {
                int o = bn + wn + nt * 8 + lc;
                float v0 = (acc[mt][nt][2 * i + 0] + __ldg(bias + o))     * scale;
                float v1 = (acc[mt][nt][2 * i + 1] + __ldg(bias + o + 1)) * scale;
                int hh = o >> 6, dd = o & 63;
                if (z < 2) {
                    size_t off = ((size_t)(nb2 * NH + hh) * SEQ + q) * DKH + dd;
                    *(uint32_t*)(out + off) = pack2h(v0, v1);
                } else {
                    size_t off = ((size_t)(nb2 * NH + hh) * DKH + dd) * SEQ + q;
                    out[off]       = __float2half_rn(v0);
                    out[off + SEQ] = __float2half_rn(v1);
                }
            }
        }
    }
}

// ---- O projection: fp32 output ----
__global__ void __launch_bounds__(256, 2) proj_o_kernel(const float* __restrict__ bias,
                                                        float* __restrict__ out)
{
    extern __shared__ __align__(128) char smem[];
    uint32_t sb = smem_u32(smem);
    int tid = threadIdx.x, lane = tid & 31, warp = tid >> 5;
    int bm = blockIdx.y * 128, bn = blockIdx.x * 128;

    float acc[4][4][4];
#pragma unroll
    for (int i = 0; i < 4; i++)
#pragma unroll
        for (int j = 0; j < 4; j++)
#pragma unroll
            for (int t = 0; t < 4; t++) acc[i][j][t] = 0.0f;

    proj_mainloop(sb, tid, lane, warp, g_ctx, g_wo, bm, bn, acc);

    int wm = (warp >> 2) * 64, wn = (warp & 3) * 32;
    int lr = lane >> 2, lc = (lane & 3) * 2;
#pragma unroll
    for (int mt = 0; mt < 4; mt++) {
#pragma unroll
        for (int i = 0; i < 2; i++) {
            int m = bm + wm + mt * 16 + lr + i * 8;
#pragma unroll
            for (int nt = 0; nt < 4; nt++) {
                int o = bn + wn + nt * 8 + lc;
                float v0 = acc[mt][nt][2 * i + 0] + __ldg(bias + o);
                float v1 = acc[mt][nt][2 * i + 1] + __ldg(bias + o + 1);
                *(float2*)(out + (size_t)m * DM + o) = make_float2(v0, v1);
            }
        }
    }
}

// ===================== attention (R10 base + combined lsum ones-MMA) =====================
// CTA = 128 q rows x 1 head, 8 warps x 16 rows, 256 threads, 2 CTAs/SM.
// KV tiles of 64, 2-stage cp.async. Q pre-scaled by 0.125*log2(e).
// Softmax: cvt f32->f16x2, ex2.approx.f16x2, zero-mask post-exp.
// Row sums: accumulate spa = sum_g pa (HADD2, off critical path), ONE ones-MMA/tile.
#define ATT_SMEM (16384 + 2 * 16384)

__device__ __forceinline__ void att_load_kv(
    uint32_t sbase, int tid, int kt,
    const __half* __restrict__ kk, const __half* __restrict__ vv)
{
#pragma unroll
    for (int i = 0; i < 2; i++) {
        int idx = tid + i * 256;          // 0..511 -> 64 rows x 8 chunks
        int r = idx >> 3, ch = idx & 7;
        uint32_t d = sbase + ASWZ(r, ch);
        CP16(d,        kk + (size_t)(kt * 64 + r) * DKH + ch * 8);
        CP16(d + 8192, vv + (size_t)r * SEQ + kt * 64 + ch * 8);
    }
}

__global__ void __launch_bounds__(256, 2) attn_kernel()
{
    extern __shared__ __align__(128) char smem[];
    uint32_t sb = smem_u32(smem);
    int tid = threadIdx.x, lane = tid & 31, warp = tid >> 5;   // warp 0..7
    int qt = blockIdx.x, h = blockIdx.y, n = blockIdx.z;

    const __half* qp = g_q  + ((size_t)(n * NH + h) * SEQ + qt * 128) * DKH;
    const __half* kp = g_k  + (size_t)(n * NH + h) * SEQ * DKH;
    const __half* vp = g_vT + (size_t)(n * NH + h) * DKH * SEQ;
    const uint32_t* mbase = g_mbits + (size_t)n * SEQ * 64;

    // Q tile @0 + KV tile 0 -> one cp.async group
#pragma unroll
    for (int i = 0; i < 4; i++) {
        int idx = tid + i * 256;          // 0..1023 -> 128 rows x 8 chunks
        int r = idx >> 3, ch = idx & 7;
        CP16(sb + ASWZ(r, ch), qp + (size_t)r * DKH + ch * 8);
    }
    att_load_kv(sb + 16384, tid, 0, kp, vp);
    CPCOMMIT();

    int a_r = (lane & 7) + ((lane >> 3) & 1) * 8;
    int a_c = lane >> 4;
    int b_r = (lane & 7) + (lane >> 4) * 8;
    int b_c = (lane >> 3) & 1;
    int lr = lane >> 2, lc = (lane & 3) * 2;
    int q0 = qt * 128 + warp * 16 + lr;   // global q of rows d0/d1

    uint32_t qa[4][4];                    // [k16][reg]
    float oacc[8][4];
    float lacc[4];                        // row-sum accumulators (combined ones-MMA)
#pragma unroll
    for (int ng = 0; ng < 8; ng++)
#pragma unroll
        for (int t = 0; t < 4; t++) oacc[ng][t] = 0.0f;
#pragma unroll
    for (int t = 0; t < 4; t++) lacc[t] = 0.0f;

    for (int kt = 0; kt < 32; kt++) {
        CPWAIT0();
        __syncthreads();
        if (kt == 0) {
#pragma unroll
            for (int k16 = 0; k16 < 4; k16++)
                ldsm4(qa[k16], sb + ASWZ(warp * 16 + a_r, k16 * 2 + a_c));
        }
        // prefetch mask words (rows lr, lr+8)
        uint2 mw0 = *(const uint2*)(mbase + (size_t)q0 * 64 + 2 * kt);
        uint2 mw1 = *(const uint2*)(mbase + (size_t)(q0 + 8) * 64 + 2 * kt);

        if (kt + 1 < 32) {
            att_load_kv(sb + 16384 + ((kt + 1) & 1) * 16384, tid, kt + 1, kp, vp);
            CPCOMMIT();
        }
        uint32_t kvb = sb + 16384 + (kt & 1) * 16384;

        // ---- S = Q K^T (full tile: 8 independent accumulator chains) ----
        float sacc[8][4];
#pragma unroll
        for (int ng = 0; ng < 8; ng++)
#pragma unroll
            for (int t = 0; t < 4; t++) sacc[ng][t] = 0.0f;

#pragma unroll
        for (int k16 = 0; k16 < 4; k16++) {
#pragma unroll
            for (int ngp = 0; ngp < 4; ngp++) {
                uint32_t bh[4];
                ldsm4(bh, kvb + ASWZ(ngp * 16 + b_r, k16 * 2 + b_c));
                mma_fp16(sacc[2 * ngp],     qa[k16], bh[0], bh[1]);
                mma_fp16(sacc[2 * ngp + 1], qa[k16], bh[2], bh[3]);
            }
        }

        // ---- softmax (f16x2 ex2, zero-mask) + PV, fused per kv16 group ----
        uint32_t spa[4] = {0u, 0u, 0u, 0u};   // sum of pa over groups (for row sums)
#pragma unroll
        for (int g = 0; g < 4; g++) {
            uint32_t w0 = (g < 2) ? mw0.x : mw0.y;
            uint32_t w1 = (g < 2) ? mw1.x : mw1.y;
            int sh = ((g & 1) << 4) + lc;
            const float* s0 = sacc[2 * g];
            const float* s1 = sacc[2 * g + 1];
            uint32_t pa[4];
            pa[0] = ex2h2(cvt2h(s0[1], s0[0])) & ~zmask2(w0, sh);
            pa[1] = ex2h2(cvt2h(s0[3], s0[2])) & ~zmask2(w1, sh);
            pa[2] = ex2h2(cvt2h(s1[1], s1[0])) & ~zmask2(w0, sh + 8);
            pa[3] = ex2h2(cvt2h(s1[3], s1[2])) & ~zmask2(w1, sh + 8);
            spa[0] = hadd2(spa[0], pa[0]);
            spa[1] = hadd2(spa[1], pa[1]);
            spa[2] = hadd2(spa[2], pa[2]);
            spa[3] = hadd2(spa[3], pa[3]);
#pragma unroll
            for (int ngd = 0; ngd < 4; ngd++) {
                uint32_t bh[4];
                ldsm4(bh, kvb + 8192 + ASWZ(ngd * 16 + b_r, g * 2 + b_c));
                mma_fp16(oacc[2 * ngd],     pa, bh[0], bh[1]);
                mma_fp16(oacc[2 * ngd + 1], pa, bh[2], bh[3]);
            }
        }
        mma_fp16(lacc, spa, ONES_H2, ONES_H2);   // ONE row-sum MMA per tile
    }

    // ---- epilogue (lacc holds full row sums; no shuffles) ----
    float i0 = 1.0f / lacc[0];    // row lr
    float i1 = 1.0f / lacc[2];    // row lr+8
    size_t row0 = ((size_t)n * SEQ + q0) * DM + h * DKH;
#pragma unroll
    for (int ng = 0; ng < 8; ng++) {
        int col = ng * 8 + lc;
        *(uint32_t*)(g_ctx + row0 + col)          = pack2h(oacc[ng][0] * i0, oacc[ng][1] * i0);
        *(uint32_t*)(g_ctx + row0 + 8 * DM + col) = pack2h(oacc[ng][2] * i1, oacc[ng][3] * i1);
    }
}

// ===================== launch =====================
extern "C" void kernel_launch(void* const* d_in, const int* in_sizes, int n_in,
                              void* d_out, int out_size)
{
    const float* q   = (const float*)d_in[0];
    const float* k   = (const float*)d_in[1];
    const float* v   = (const float*)d_in[2];
    const int*   msk = (const int*)d_in[3];
    const float* Wq  = (const float*)d_in[4];
    const float* bq  = (const float*)d_in[5];
    const float* Wk  = (const float*)d_in[6];
    const float* bk  = (const float*)d_in[7];
    const float* Wv  = (const float*)d_in[8];
    const float* bv  = (const float*)d_in[9];
    const float* Wo  = (const float*)d_in[10];
    const float* bo  = (const float*)d_in[11];
    float* out = (float*)d_out;

    cudaFuncSetAttribute(proj_qkv_kernel, cudaFuncAttributeMaxDynamicSharedMemorySize, PROJ_SMEM);
    cudaFuncSetAttribute(proj_o_kernel,   cudaFuncAttributeMaxDynamicSharedMemorySize, PROJ_SMEM);
    cudaFuncSetAttribute(attn_kernel,     cudaFuncAttributeMaxDynamicSharedMemorySize, ATT_SMEM);

    const int TOT4 = 3 * (NB * SEQ * DM / 4) + 4 * (DM * DM / 4);
    cvt_all_kernel<<<TOT4 / 256, 256>>>(q, k, v, Wq, Wk, Wv, Wo);
    maskpack_kernel<<<NB * SEQ * 64 / 256, 256>>>(msk);

    dim3 pgrid(DM / 128, NB * SEQ / 128, 3);
    proj_qkv_kernel<<<pgrid, 256, PROJ_SMEM>>>(bq, bk, bv);

    attn_kernel<<<dim3(SEQ / 128, NH, NB), 256, ATT_SMEM>>>();

    dim3 ogrid(DM / 128, NB * SEQ / 128);
    proj_o_kernel<<<ogrid, 256, PROJ_SMEM>>>(bo, out);
}

// round 16
// speedup vs baseline: 1.0524x; 1.0256x over previous
#include <cuda_runtime.h>
#include <cuda_fp16.h>
#include <stdint.h>

#define NB   2
#define SEQ  2048
#define DM   1024
#define NH   16
#define DKH  64

// ===================== device scratch (no allocations) =====================
__device__ __align__(16) __half g_xq[(size_t)NB*SEQ*DM];
__device__ __align__(16) __half g_xk[(size_t)NB*SEQ*DM];
__device__ __align__(16) __half g_xv[(size_t)NB*SEQ*DM];
__device__ __align__(16) __half g_wq[(size_t)DM*DM];
__device__ __align__(16) __half g_wk[(size_t)DM*DM];
__device__ __align__(16) __half g_wv[(size_t)DM*DM];
__device__ __align__(16) __half g_wo[(size_t)DM*DM];
__device__ __align__(16) __half g_q[(size_t)NB*NH*SEQ*DKH];     // pre-scaled by 0.125*log2(e)
__device__ __align__(16) __half g_k[(size_t)NB*NH*SEQ*DKH];
__device__ __align__(16) __half g_vT[(size_t)NB*NH*DKH*SEQ];
__device__ __align__(16) __half g_ctx[(size_t)NB*SEQ*DM];
__device__ uint32_t g_mbits[(size_t)NB*SEQ*64];   // [n][q][kv/32], bit=1 -> masked

// ===================== helpers =====================
__device__ __forceinline__ uint32_t smem_u32(const void* p) {
    uint32_t a;
    asm("{ .reg .u64 t; cvta.to.shared.u64 t, %1; cvt.u32.u64 %0, t; }" : "=r"(a) : "l"(p));
    return a;
}
__device__ __forceinline__ void ldsm4(uint32_t* r, uint32_t a) {
    asm volatile("ldmatrix.sync.aligned.m8n8.x4.shared.b16 {%0,%1,%2,%3}, [%4];"
        : "=r"(r[0]), "=r"(r[1]), "=r"(r[2]), "=r"(r[3]) : "r"(a));
}
__device__ __forceinline__ void mma_fp16(float* d, const uint32_t* a, uint32_t b0, uint32_t b1) {
    asm volatile(
        "mma.sync.aligned.m16n8k16.row.col.f32.f16.f16.f32 "
        "{%0,%1,%2,%3}, {%4,%5,%6,%7}, {%8,%9}, {%0,%1,%2,%3};"
        : "+f"(d[0]), "+f"(d[1]), "+f"(d[2]), "+f"(d[3])
        : "r"(a[0]), "r"(a[1]), "r"(a[2]), "r"(a[3]), "r"(b0), "r"(b1));
}
// pack two f32 into half2 (lo = l, hi = h)
__device__ __forceinline__ uint32_t cvt2h(float h, float l) {
    uint32_t d;
    asm("cvt.rn.f16x2.f32 %0, %1, %2;" : "=r"(d) : "f"(h), "f"(l));
    return d;
}
__device__ __forceinline__ uint32_t ex2h2(uint32_t x) {
    uint32_t d;
    asm("ex2.approx.f16x2 %0, %1;" : "=r"(d) : "r"(x));
    return d;
}
// AND-pattern: halfword k is 0xFFFF where mask bit (sh+k) is SET (masked)
__device__ __forceinline__ uint32_t zmask2(uint32_t w, int sh) {
    uint32_t t = w >> sh;
    return (t & 1u) * 0x0000FFFFu + (t & 2u) * 0x7FFF8000u;
}
#define CP16(dst, src)  asm volatile("cp.async.cg.shared.global [%0], [%1], 16;" :: "r"(dst), "l"(src) : "memory")
#define CPCOMMIT()      asm volatile("cp.async.commit_group;" ::: "memory")
#define CPWAIT0()       asm volatile("cp.async.wait_group 0;" ::: "memory")

// 128-byte rows: SW128 swizzle on 16B chunks
#define ASWZ(r, ch) ((uint32_t)(((r) << 7) + ((((ch) ^ ((r) & 7))) << 4)))

__device__ __forceinline__ uint32_t pack2h(float a, float b) {
    __half2 h = __floats2half2_rn(a, b);
    return *(uint32_t*)&h;
}

#define ONES_H2 0x3C003C00u   // half2 (1.0, 1.0)

// ===================== prep: ONE fused convert + maskpack kernel =====================
#define INP4 (NB * SEQ * DM / 4)     // 1048576 float4 per input
#define W4   (DM * DM / 4)           // 262144 per weight
#define TOT4 (3 * INP4 + 4 * W4)     // 4194304
#define MW   (NB * SEQ * 64)         // 262144 mask words

__global__ void prep_kernel(
    const float* __restrict__ q,  const float* __restrict__ k,  const float* __restrict__ v,
    const float* __restrict__ Wq, const float* __restrict__ Wk, const float* __restrict__ Wv,
    const float* __restrict__ Wo, const int* __restrict__ mask)
{
    int gid = blockIdx.x * blockDim.x + threadIdx.x;
    if (gid < TOT4) {
        const float* src;
        __half* dst;
        int off;
        if (gid < 3 * INP4) {
            int seg = gid / INP4;
            off = gid - seg * INP4;
            src = (seg == 0) ? q : (seg == 1) ? k : v;
            dst = (seg == 0) ? g_xq : (seg == 1) ? g_xk : g_xv;
        } else {
            int r = gid - 3 * INP4;
            int seg = r / W4;
            off = r - seg * W4;
            src = (seg == 0) ? Wq : (seg == 1) ? Wk : (seg == 2) ? Wv : Wo;
            dst = (seg == 0) ? g_wq : (seg == 1) ? g_wk : (seg == 2) ? g_wv : g_wo;
        }
        float4 x = ((const float4*)src)[off];
        uint2 o;
        o.x = pack2h(x.x, x.y);
        o.y = pack2h(x.z, x.w);
        ((uint2*)dst)[off] = o;
    } else {
        int w = gid - TOT4;
        if (w >= MW) return;
        const int* p = mask + (size_t)w * 32;
        uint32_t bits = 0;
#pragma unroll
        for (int j = 0; j < 32; j += 4) {
            int4 m4 = *(const int4*)(p + j);
            bits |= (m4.x ? 1u : 0u) << j       | (m4.y ? 1u : 0u) << (j + 1)
                  | (m4.z ? 1u : 0u) << (j + 2) | (m4.w ? 1u : 0u) << (j + 3);
        }
        g_mbits[w] = bits;
    }
}

// ===================== projection GEMM core (2-stage cp.async, de-phased) =====================
#define PROJ_SMEM 65536

__device__ __forceinline__ void proj_load(
    uint32_t sbase, int tid, int k0,
    const __half* __restrict__ A, const __half* __restrict__ W, int bm, int bn)
{
#pragma unroll
    for (int i = 0; i < 4; i++) {
        int idx = tid + i * 256;          // 0..1023 -> 128 rows x 8 chunks
        int r = idx >> 3, ch = idx & 7;
        uint32_t d = sbase + ASWZ(r, ch);
        CP16(d,         A + (size_t)(bm + r) * DM + k0 + ch * 8);
        CP16(d + 16384, W + (size_t)(bn + r) * DM + k0 + ch * 8);
    }
}

__device__ __forceinline__ void proj_mainloop(
    uint32_t sb, int tid, int lane, int warp, int c0,
    const __half* __restrict__ A, const __half* __restrict__ W,
    int bm, int bn, float acc[4][4][4])
{
    int wm = (warp >> 2) * 64;
    int wn = (warp & 3) * 32;
    int a_r = (lane & 7) + ((lane >> 3) & 1) * 8;
    int a_c = lane >> 4;
    int b_r = (lane & 7) + (lane >> 4) * 8;
    int b_c = (lane >> 3) & 1;

    proj_load(sb, tid, c0 * 64, A, W, bm, bn);
    CPCOMMIT();

    for (int c = 0; c < 16; c++) {
        CPWAIT0();
        __syncthreads();
        if (c + 1 < 16) {
            int cr = (c + 1 + c0) & 15;
            proj_load(sb + ((c + 1) & 1) * 32768, tid, cr * 64, A, W, bm, bn);
            CPCOMMIT();
        }
        uint32_t ab = sb + (c & 1) * 32768;
        uint32_t wb = ab + 16384;
#pragma unroll
        for (int k16 = 0; k16 < 4; k16++) {
            uint32_t bh0[4], bh1[4];
            ldsm4(bh0, wb + ASWZ(wn + b_r,      k16 * 2 + b_c));
            ldsm4(bh1, wb + ASWZ(wn + 16 + b_r, k16 * 2 + b_c));
#pragma unroll
            for (int mt = 0; mt < 4; mt++) {
                uint32_t ah[4];
                ldsm4(ah, ab + ASWZ(wm + mt * 16 + a_r, k16 * 2 + a_c));
                mma_fp16(acc[mt][0], ah, bh0[0], bh0[1]);
                mma_fp16(acc[mt][1], ah, bh0[2], bh0[3]);
                mma_fp16(acc[mt][2], ah, bh1[0], bh1[1]);
                mma_fp16(acc[mt][3], ah, bh1[2], bh1[3]);
            }
        }
    }
}

// ---- fused Q/K/V projection: grid.z selects which ----
__global__ void __launch_bounds__(256, 2) proj_qkv_kernel(
    const float* __restrict__ bq, const float* __restrict__ bk, const float* __restrict__ bv)
{
    int z = blockIdx.z;
    const __half* A = (z == 0) ? g_xq : (z == 1) ? g_xk : g_xv;
    const __half* W = (z == 0) ? g_wq : (z == 1) ? g_wk : g_wv;
    const float* bias = (z == 0) ? bq : (z == 1) ? bk : bv;
    __half* out = (z == 0) ? g_q : (z == 1) ? g_k : g_vT;
    float scale = (z == 0) ? 0.18033688011112043f : 1.0f;   // 0.125 * log2(e) for Q

    extern __shared__ __align__(128) char smem[];
    uint32_t sb = smem_u32(smem);
    int tid = threadIdx.x, lane = tid & 31, warp = tid >> 5;
    int bm = blockIdx.y * 128, bn = blockIdx.x * 128;
    int fbid = blockIdx.x + (blockIdx.y << 3) + (blockIdx.z << 8);
    int c0 = ((fbid / 148) & 1) << 3;     // de-phase co-resident CTAs

    float acc[4][4][4];
#pragma unroll
    for (int i = 0; i < 4; i++)
#pragma unroll
        for (int j = 0; j < 4; j++)
#pragma unroll
            for (int t = 0; t < 4; t++) acc[i][j][t] = 0.0f;

    proj_mainloop(sb, tid, lane, warp, c0, A, W, bm, bn, acc);

    int wm = (warp >> 2) * 64, wn = (warp & 3) * 32;
    int lr = lane >> 2, lc = (lane & 3) * 2;

    if (z < 2) {
        // Q/K: direct 4B stores, head-major [n][h][q][d]
#pragma unroll
        for (int mt = 0; mt < 4; mt++) {
#pragma unroll
            for (int i = 0; i < 2; i++) {
                int m = bm + wm + mt * 16 + lr + i * 8;
                int nb2 = m >> 11, qrow = m & (SEQ - 1);
#pragma unroll
                for (int nt = 0; nt < 4; nt++) {
                    int o = bn + wn + nt * 8 + lc;
                    float v0 = (acc[mt][nt][2 * i + 0] + __ldg(bias + o))     * scale;
                    float v1 = (acc[mt][nt][2 * i + 1] + __ldg(bias + o + 1)) * scale;
                    int hh = o >> 6, dd = o & 63;
                    size_t off = ((size_t)(nb2 * NH + hh) * SEQ + qrow) * DKH + dd;
                    *(uint32_t*)(out + off) = pack2h(v0, v1);
                }
            }
        }
    } else {
        // V: transpose via smem, then coalesced 16B row stores to vT [n][h][d][q]
        __syncthreads();   // mainloop smem reads done in all warps
        __half* stg = (__half*)smem;            // [128 dd][stride 132] halves
#pragma unroll
        for (int mt = 0; mt < 4; mt++) {
#pragma unroll
            for (int i = 0; i < 2; i++) {
                int qq_l = wm + mt * 16 + lr + i * 8;     // local q row 0..127
#pragma unroll
                for (int nt = 0; nt < 4; nt++) {
                    int dd_l = wn + nt * 8 + lc;          // local col 0..127
                    int o = bn + dd_l;
                    float v0 = acc[mt][nt][2 * i + 0] + __ldg(bias + o);
                    float v1 = acc[mt][nt][2 * i + 1] + __ldg(bias + o + 1);
                    stg[(dd_l + 0) * 132 + qq_l] = __float2half_rn(v0);
                    stg[(dd_l + 1) * 132 + qq_l] = __float2half_rn(v1);
                }
            }
        }
        __syncthreads();
        int row = tid >> 1;                  // dd_local 0..127
        int seg = (tid & 1) * 64;            // q half
        int o = bn + row;
        int hh = o >> 6, dd = o & 63;
        int nb2 = bm >> 11, qbase = bm & (SEQ - 1);
        __half* dst = out + ((size_t)(nb2 * NH + hh) * DKH + dd) * SEQ + qbase + seg;
        const __half* srcp = stg + row * 132 + seg;
#pragma unroll
        for (int j = 0; j < 64; j += 8) {
            uint2 a = *(const uint2*)(srcp + j);
            uint2 b = *(const uint2*)(srcp + j + 4);
            uint4 w4v;
            w4v.x = a.x; w4v.y = a.y; w4v.z = b.x; w4v.w = b.y;
            *(uint4*)(dst + j) = w4v;
        }
    }
}

// ---- O projection: fp32 output ----
__global__ void __launch_bounds__(256, 2) proj_o_kernel(const float* __restrict__ bias,
                                                        float* __restrict__ out)
{
    extern __shared__ __align__(128) char smem[];
    uint32_t sb = smem_u32(smem);
    int tid = threadIdx.x, lane = tid & 31, warp = tid >> 5;
    int bm = blockIdx.y * 128, bn = blockIdx.x * 128;
    int fbid = blockIdx.x + (blockIdx.y << 3);
    int c0 = ((fbid / 148) & 1) << 3;

    float acc[4][4][4];
#pragma unroll
    for (int i = 0; i < 4; i++)
#pragma unroll
        for (int j = 0; j < 4; j++)
#pragma unroll
            for (int t = 0; t < 4; t++) acc[i][j][t] = 0.0f;

    proj_mainloop(sb, tid, lane, warp, c0, g_ctx, g_wo, bm, bn, acc);

    int wm = (warp >> 2) * 64, wn = (warp & 3) * 32;
    int lr = lane >> 2, lc = (lane & 3) * 2;
#pragma unroll
    for (int mt = 0; mt < 4; mt++) {
#pragma unroll
        for (int i = 0; i < 2; i++) {
            int m = bm + wm + mt * 16 + lr + i * 8;
#pragma unroll
            for (int nt = 0; nt < 4; nt++) {
                int o = bn + wn + nt * 8 + lc;
                float v0 = acc[mt][nt][2 * i + 0] + __ldg(bias + o);
                float v1 = acc[mt][nt][2 * i + 1] + __ldg(bias + o + 1);
                *(float2*)(out + (size_t)m * DM + o) = make_float2(v0, v1);
            }
        }
    }
}

// ===================== attention (R9/R10 best: 32-row warps, de-phased) =====================
// CTA = 128 q rows x 1 head, 4 warps x 32 rows. KV tiles of 64, 2-stage cp.async.
// Co-resident CTAs start the KV sweep 16 tiles apart (sum order is free).
// Q pre-scaled by 0.125*log2(e). Softmax: f32->f16x2 cvt, ex2.approx.f16x2,
// masked entries zeroed post-exp. Row sums via ones-MMA (fp32 acc, no shuffles).
#define ATT_SMEM (16384 + 2 * 16384)

__device__ __forceinline__ void att_load_kv(
    uint32_t sbase, int tid, int kt,
    const __half* __restrict__ kk, const __half* __restrict__ vv)
{
#pragma unroll
    for (int i = 0; i < 4; i++) {
        int idx = tid + i * 128;          // 0..511 -> 64 rows x 8 chunks
        int r = idx >> 3, ch = idx & 7;
        uint32_t d = sbase + ASWZ(r, ch);
        CP16(d,        kk + (size_t)(kt * 64 + r) * DKH + ch * 8);
        CP16(d + 8192, vv + (size_t)r * SEQ + kt * 64 + ch * 8);
    }
}

__global__ void __launch_bounds__(128, 2) attn_kernel()
{
    extern __shared__ __align__(128) char smem[];
    uint32_t sb = smem_u32(smem);
    int tid = threadIdx.x, lane = tid & 31, warp = tid >> 5;   // warp 0..3
    int qt = blockIdx.x, h = blockIdx.y, n = blockIdx.z;
    int fbid = blockIdx.x + (blockIdx.y << 4) + (blockIdx.z << 8);
    int kt0 = ((fbid / 148) & 1) << 4;    // de-phase co-resident CTAs

    const __half* qp = g_q  + ((size_t)(n * NH + h) * SEQ + qt * 128) * DKH;
    const __half* kp = g_k  + (size_t)(n * NH + h) * SEQ * DKH;
    const __half* vp = g_vT + (size_t)(n * NH + h) * DKH * SEQ;
    const uint32_t* mbase = g_mbits + (size_t)n * SEQ * 64;

    // Q tile @0 + KV tile kt0 -> one cp.async group
#pragma unroll
    for (int i = 0; i < 8; i++) {
        int idx = tid + i * 128;          // 0..1023 -> 128 rows x 8 chunks
        int r = idx >> 3, ch = idx & 7;
        CP16(sb + ASWZ(r, ch), qp + (size_t)r * DKH + ch * 8);
    }
    att_load_kv(sb + 16384, tid, kt0, kp, vp);
    CPCOMMIT();

    int a_r = (lane & 7) + ((lane >> 3) & 1) * 8;
    int a_c = lane >> 4;
    int b_r = (lane & 7) + (lane >> 4) * 8;
    int b_c = (lane >> 3) & 1;
    int lr = lane >> 2, lc = (lane & 3) * 2;
    int q0 = qt * 128 + warp * 32 + lr;

    uint32_t qa[4][2][4];                 // [k16][mfrag][reg]
    float oacc[2][8][4];
    float lacc[2][4];                     // row-sum accumulators (ones-MMA)
#pragma unroll
    for (int mi = 0; mi < 2; mi++) {
#pragma unroll
        for (int ng = 0; ng < 8; ng++)
#pragma unroll
            for (int t = 0; t < 4; t++) oacc[mi][ng][t] = 0.0f;
#pragma unroll
        for (int t = 0; t < 4; t++) lacc[mi][t] = 0.0f;
    }

    for (int kt = 0; kt < 32; kt++) {
        int ktr = (kt + kt0) & 31;        // actual KV tile
        CPWAIT0();
        __syncthreads();
        if (kt == 0) {
#pragma unroll
            for (int k16 = 0; k16 < 4; k16++)
#pragma unroll
                for (int mi = 0; mi < 2; mi++)
                    ldsm4(qa[k16][mi], sb + ASWZ(warp * 32 + mi * 16 + a_r, k16 * 2 + a_c));
        }
        // prefetch mask words (rows lr, lr+8 of each 16-row m-frag)
        uint2 mw[2][2];
#pragma unroll
        for (int mi = 0; mi < 2; mi++)
#pragma unroll
            for (int ri = 0; ri < 2; ri++)
                mw[mi][ri] = *(const uint2*)(mbase + (size_t)(q0 + mi * 16 + ri * 8) * 64 + 2 * ktr);

        if (kt + 1 < 32) {
            att_load_kv(sb + 16384 + ((kt + 1) & 1) * 16384, tid, (kt + 1 + kt0) & 31, kp, vp);
            CPCOMMIT();
        }
        uint32_t kvb = sb + 16384 + (kt & 1) * 16384;

        // ---- S = Q K^T (full tile: 16 independent accumulator chains) ----
        float sacc[2][8][4];
#pragma unroll
        for (int mi = 0; mi < 2; mi++)
#pragma unroll
            for (int ng = 0; ng < 8; ng++)
#pragma unroll
                for (int t = 0; t < 4; t++) sacc[mi][ng][t] = 0.0f;

#pragma unroll
        for (int k16 = 0; k16 < 4; k16++) {
#pragma unroll
            for (int ngp = 0; ngp < 4; ngp++) {
                uint32_t bh[4];
                ldsm4(bh, kvb + ASWZ(ngp * 16 + b_r, k16 * 2 + b_c));
                mma_fp16(sacc[0][2 * ngp],     qa[k16][0], bh[0], bh[1]);
                mma_fp16(sacc[0][2 * ngp + 1], qa[k16][0], bh[2], bh[3]);
                mma_fp16(sacc[1][2 * ngp],     qa[k16][1], bh[0], bh[1]);
                mma_fp16(sacc[1][2 * ngp + 1], qa[k16][1], bh[2], bh[3]);
            }
        }

        // ---- softmax (f16x2 ex2, zero-mask) + PV, fused per kv16 group ----
#pragma unroll
        for (int g = 0; g < 4; g++) {
            uint32_t pa[2][4];
#pragma unroll
            for (int mi = 0; mi < 2; mi++) {
                uint32_t w0 = (g < 2) ? mw[mi][0].x : mw[mi][0].y;
                uint32_t w1 = (g < 2) ? mw[mi][1].x : mw[mi][1].y;
                int sh = ((g & 1) << 4) + lc;
                const float* s0 = sacc[mi][2 * g];
                const float* s1 = sacc[mi][2 * g + 1];
                pa[mi][0] = ex2h2(cvt2h(s0[1], s0[0])) & ~zmask2(w0, sh);
                pa[mi][1] = ex2h2(cvt2h(s0[3], s0[2])) & ~zmask2(w1, sh);
                pa[mi][2] = ex2h2(cvt2h(s1[1], s1[0])) & ~zmask2(w0, sh + 8);
                pa[mi][3] = ex2h2(cvt2h(s1[3], s1[2])) & ~zmask2(w1, sh + 8);
                mma_fp16(lacc[mi], pa[mi], ONES_H2, ONES_H2);   // row sums
            }
#pragma unroll
            for (int ngd = 0; ngd < 4; ngd++) {
                uint32_t bh[4];
                ldsm4(bh, kvb + 8192 + ASWZ(ngd * 16 + b_r, g * 2 + b_c));
                mma_fp16(oacc[0][2 * ngd],     pa[0], bh[0], bh[1]);
                mma_fp16(oacc[0][2 * ngd + 1], pa[0], bh[2], bh[3]);
                mma_fp16(oacc[1][2 * ngd],     pa[1], bh[0], bh[1]);
                mma_fp16(oacc[1][2 * ngd + 1], pa[1], bh[2], bh[3]);
            }
        }
    }

    // ---- epilogue (lacc holds full row sums; no shuffles) ----
#pragma unroll
    for (int mi = 0; mi < 2; mi++) {
        float i0 = 1.0f / lacc[mi][0];    // row lr
        float i1 = 1.0f / lacc[mi][2];    // row lr+8
        size_t row0 = ((size_t)n * SEQ + q0 + mi * 16) * DM + h * DKH;
#pragma unroll
        for (int ng = 0; ng < 8; ng++) {
            int col = ng * 8 + lc;
            *(uint32_t*)(g_ctx + row0 + col)          = pack2h(oacc[mi][ng][0] * i0, oacc[mi][ng][1] * i0);
            *(uint32_t*)(g_ctx + row0 + 8 * DM + col) = pack2h(oacc[mi][ng][2] * i1, oacc[mi][ng][3] * i1);
        }
    }
}

// ===================== launch =====================
extern "C" void kernel_launch(void* const* d_in, const int* in_sizes, int n_in,
                              void* d_out, int out_size)
{
    const float* q   = (const float*)d_in[0];
    const float* k   = (const float*)d_in[1];
    const float* v   = (const float*)d_in[2];
    const int*   msk = (const int*)d_in[3];
    const float* Wq  = (const float*)d_in[4];
    const float* bq  = (const float*)d_in[5];
    const float* Wk  = (const float*)d_in[6];
    const float* bk  = (const float*)d_in[7];
    const float* Wv  = (const float*)d_in[8];
    const float* bv  = (const float*)d_in[9];
    const float* Wo  = (const float*)d_in[10];
    const float* bo  = (const float*)d_in[11];
    float* out = (float*)d_out;

    cudaFuncSetAttribute(proj_qkv_kernel, cudaFuncAttributeMaxDynamicSharedMemorySize, PROJ_SMEM);
    cudaFuncSetAttribute(proj_o_kernel,   cudaFuncAttributeMaxDynamicSharedMemorySize, PROJ_SMEM);
    cudaFuncSetAttribute(attn_kernel,     cudaFuncAttributeMaxDynamicSharedMemorySize, ATT_SMEM);

    // ONE prep launch: converts + mask pack
    prep_kernel<<<(TOT4 + MW + 255) / 256, 256>>>(q, k, v, Wq, Wk, Wv, Wo, msk);

    dim3 pgrid(DM / 128, NB * SEQ / 128, 3);
    proj_qkv_kernel<<<pgrid, 256, PROJ_SMEM>>>(bq, bk, bv);

    attn_kernel<<<dim3(SEQ / 128, NH, NB), 128, ATT_SMEM>>>();

    dim3 ogrid(DM / 128, NB * SEQ / 128);
    proj_o_kernel<<<ogrid, 256, PROJ_SMEM>>>(bo, out);
}